// round 14
// baseline (speedup 1.0000x reference)
#include <cuda_runtime.h>
#include <cuda_bf16.h>
#include <cstdint>
#include <math.h>

// Problem constants
#define BWIN   2048
#define SEQ    64
#define DIM    256
#define HEADS  8
#define HD     32
#define NW     64
#define KDIM   256
#define TBL    225
#define CPBH   512

// Scratch (device globals)
__device__ float g_Q[BWIN * HEADS * SEQ * HD];
__device__ float g_K[BWIN * HEADS * SEQ * HD];
__device__ float g_V[BWIN * HEADS * SEQ * HD];
__device__ float g_table[TBL * HEADS];
__device__ float g_bias[HEADS * SEQ * SEQ];
__device__ float g_bm[NW * HEADS * SEQ * SEQ];     // fused bias+mask

// Pre-split (packed bf16 hi/lo, granule layout) operands
__device__ uint32_t g_Xs[(size_t)BWIN * SEQ * DIM];   // 128 MB
__device__ uint32_t g_Os[(size_t)BWIN * SEQ * DIM];   // 128 MB
__device__ uint32_t g_Ws[3 * DIM * DIM];
__device__ uint32_t g_Wp[DIM * DIM];

// SW128 swizzle on byte offsets (128B rows)
#define SWZ(b) ((b) ^ (((b) >> 3) & 0x70))

__device__ __forceinline__ uint32_t smem_u32(const void* p) {
    uint32_t a;
    asm("{ .reg .u64 t; cvta.to.shared.u64 t, %1; cvt.u32.u64 %0, t; }"
        : "=r"(a) : "l"(p));
    return a;
}

#define CP16(dst_u32, src_ptr) \
    asm volatile("cp.async.cg.shared.global [%0], [%1], 16;" \
        :: "r"(dst_u32), "l"(src_ptr) : "memory")
#define CP_COMMIT() asm volatile("cp.async.commit_group;" ::: "memory")
#define CP_WAIT0()  asm volatile("cp.async.wait_group 0;" ::: "memory")
#define CP_WAIT1()  asm volatile("cp.async.wait_group 1;" ::: "memory")

// bf16 2-level split of two floats, packed as k-pair words (f0 in low half)
__device__ __forceinline__ void split2_bf(float f0, float f1,
                                          uint32_t& hi, uint32_t& lo)
{
    __nv_bfloat16 h0 = __float2bfloat16_rn(f0);
    __nv_bfloat16 h1 = __float2bfloat16_rn(f1);
    float r0 = f0 - __bfloat162float(h0);
    float r1 = f1 - __bfloat162float(h1);
    __nv_bfloat16 l0 = __float2bfloat16_rn(r0);
    __nv_bfloat16 l1 = __float2bfloat16_rn(r1);
    hi = (uint32_t)__bfloat16_as_ushort(h0) | ((uint32_t)__bfloat16_as_ushort(h1) << 16);
    lo = (uint32_t)__bfloat16_as_ushort(l0) | ((uint32_t)__bfloat16_as_ushort(l1) << 16);
}

__device__ __forceinline__ void mma16816(float* c,
    uint32_t a0, uint32_t a1, uint32_t a2, uint32_t a3,
    uint32_t b0, uint32_t b1)
{
    asm volatile(
        "mma.sync.aligned.m16n8k16.row.col.f32.bf16.bf16.f32 "
        "{%0,%1,%2,%3},{%4,%5,%6,%7},{%8,%9},{%0,%1,%2,%3};"
        : "+f"(c[0]), "+f"(c[1]), "+f"(c[2]), "+f"(c[3])
        : "r"(a0), "r"(a1), "r"(a2), "r"(a3), "r"(b0), "r"(b1));
}

// ---------------------------------------------------------------------------
// split_pack: fp32 rows -> packed bf16 hi/lo granule layout.
// ---------------------------------------------------------------------------
__global__ __launch_bounds__(256) void split_pack(
    const float* __restrict__ src, uint32_t* __restrict__ dst, int n_granules)
{
    int gidx = blockIdx.x * 256 + threadIdx.x;
    if (gidx >= n_granules) return;
    const float4* s = (const float4*)(src + (size_t)gidx * 8);
    float4 v0 = s[0], v1 = s[1];
    uint32_t h0, l0, h1, l1, h2, l2, h3, l3;
    split2_bf(v0.x, v0.y, h0, l0);
    split2_bf(v0.z, v0.w, h1, l1);
    split2_bf(v1.x, v1.y, h2, l2);
    split2_bf(v1.z, v1.w, h3, l3);
    uint4* d = (uint4*)(dst + (size_t)gidx * 8);
    d[0] = make_uint4(h0, h1, l0, l1);
    d[1] = make_uint4(h2, h3, l2, l3);
}

// ---------------------------------------------------------------------------
// Kernel 1: CPB MLP
// ---------------------------------------------------------------------------
__global__ __launch_bounds__(128) void cpb_table_kernel(
    const float* __restrict__ w1, const float* __restrict__ b1,
    const float* __restrict__ w2, const float* __restrict__ coords)
{
    int p = blockIdx.x;
    float c0 = coords[2 * p + 0];
    float c1 = coords[2 * p + 1];
    float acc[HEADS];
#pragma unroll
    for (int h = 0; h < HEADS; ++h) acc[h] = 0.f;

    for (int j = threadIdx.x; j < CPBH; j += 128) {
        float hid = fmaf(w1[2 * j], c0, fmaf(w1[2 * j + 1], c1, b1[j]));
        hid = fmaxf(hid, 0.f);
#pragma unroll
        for (int h = 0; h < HEADS; ++h)
            acc[h] = fmaf(hid, w2[h * CPBH + j], acc[h]);
    }
    int lane = threadIdx.x & 31, warp = threadIdx.x >> 5;
#pragma unroll
    for (int h = 0; h < HEADS; ++h)
#pragma unroll
        for (int off = 16; off; off >>= 1)
            acc[h] += __shfl_xor_sync(0xffffffffu, acc[h], off);

    __shared__ float red[4][HEADS];
    if (lane == 0)
#pragma unroll
        for (int h = 0; h < HEADS; ++h) red[warp][h] = acc[h];
    __syncthreads();
    if (threadIdx.x < HEADS) {
        float s = red[0][threadIdx.x] + red[1][threadIdx.x] +
                  red[2][threadIdx.x] + red[3][threadIdx.x];
        g_table[p * HEADS + threadIdx.x] = s;
    }
}

// ---------------------------------------------------------------------------
// Kernel 2: bias gather + 16*sigmoid
// ---------------------------------------------------------------------------
__global__ __launch_bounds__(256) void bias_gather_kernel(const int* __restrict__ rel_idx)
{
    int i = blockIdx.x * 256 + threadIdx.x;
    if (i >= HEADS * SEQ * SEQ) return;
    int h = i >> 12;
    int ij = i & 4095;
    float t = g_table[rel_idx[ij] * HEADS + h];
    g_bias[i] = 16.f / (1.f + expf(-t));
}

// ---------------------------------------------------------------------------
// Kernel 2b: fuse bias[h] + mask[w] -> g_bm[w][h][ij]
// ---------------------------------------------------------------------------
__global__ __launch_bounds__(256) void bm_fuse_kernel(const float* __restrict__ mask)
{
    int i = blockIdx.x * 256 + threadIdx.x;
    if (i >= NW * HEADS * SEQ * SEQ) return;
    int wh = i >> 12;
    int ij = i & 4095;
    int w = wh >> 3, h = wh & 7;
    g_bm[i] = g_bias[h * 4096 + ij] + mask[w * 4096 + ij];
}

// ---------------------------------------------------------------------------
// 3-term bf16 mma.sync GEMM, 256 threads (8 warps, warp tile 64x32),
// pre-split operands, cp.async double-buffered.
// CTA: 128x128 tile, BK=32, K=256 (8 stages). smem: 2 x (A 16KB + B 16KB).
// ---------------------------------------------------------------------------
#define GSMEM_TOTAL 65536

__global__ __launch_bounds__(256, 2) void mma_gemm(
    const float* __restrict__ q_bias, const float* __restrict__ v_bias,
    const float* __restrict__ pb, float* __restrict__ out, int mode)
{
    extern __shared__ char sm[];
    uint32_t sb = smem_u32(sm);
    const uint32_t* As = (mode == 0) ? g_Xs : g_Os;
    const uint32_t* Bsrc = (mode == 0) ? g_Ws : g_Wp;
    int tid = threadIdx.x;
    int lane = tid & 31, warp = tid >> 5;
    int m0 = blockIdx.y * 128;
    int n0 = blockIdx.x * 128;
    int wm = (warp & 1) * 64;      // warp row offset
    int wn = (warp >> 1) * 32;     // warp col offset (8 warps: 2x4)

    float acc[4][4][4];
#pragma unroll
    for (int mi = 0; mi < 4; ++mi)
#pragma unroll
        for (int ni = 0; ni < 4; ++ni)
#pragma unroll
            for (int q = 0; q < 4; ++q) acc[mi][ni][q] = 0.f;

    int g = lane >> 2;       // 0..7 row group
    int tk = lane & 3;       // 0..3 k-pair in group

    // stage: each thread cp.asyncs one full 128B packed row.
    int srow_idx = tid & 127;
    uint32_t tilebase = (tid < 128) ? 0u : 16384u;
    const uint32_t* srow_base = (tid < 128)
        ? (As + (size_t)(m0 + srow_idx) * 256)
        : (Bsrc + (size_t)(n0 + srow_idx) * 256);

#define ISSUE_STAGE(c) do { \
    uint32_t dbuf = sb + (uint32_t)(((c) & 1) * 32768) + tilebase; \
    const uint32_t* srw = srow_base + (c) * 32; \
    _Pragma("unroll") \
    for (int gp = 0; gp < 4; ++gp) { \
        uint32_t o_ = (uint32_t)(srow_idx * 128 + gp * 32); \
        CP16(dbuf + SWZ(o_), srw + gp * 8); \
        CP16(dbuf + SWZ(o_ + 16u), srw + gp * 8 + 4); \
    } \
    CP_COMMIT(); \
} while (0)

    ISSUE_STAGE(0);

    for (int c = 0; c < 8; ++c) {
        if (c < 7) { ISSUE_STAGE(c + 1); CP_WAIT1(); }
        else       { CP_WAIT0(); }
        __syncthreads();

        const char* sA = sm + (c & 1) * 32768;
        const char* sB = sA + 16384;
#pragma unroll
        for (int s = 0; s < 2; ++s) {
            uint32_t oa0 = (uint32_t)(2 * s) * 32u + ((tk >> 1) * 16u) + ((tk & 1) * 4u);
            uint32_t Ah[4][4], Al[4][4];
#pragma unroll
            for (int mi = 0; mi < 4; ++mi) {
                int r0 = wm + mi * 16 + g;
                int r1 = r0 + 8;
                uint32_t b00 = SWZ((uint32_t)(r0 * 128) + oa0);
                uint32_t b10 = SWZ((uint32_t)(r1 * 128) + oa0);
                uint32_t b01 = SWZ((uint32_t)(r0 * 128) + oa0 + 32u);
                uint32_t b11 = SWZ((uint32_t)(r1 * 128) + oa0 + 32u);
                Ah[mi][0] = *(const uint32_t*)(sA + b00);
                Ah[mi][1] = *(const uint32_t*)(sA + b10);
                Ah[mi][2] = *(const uint32_t*)(sA + b01);
                Ah[mi][3] = *(const uint32_t*)(sA + b11);
                Al[mi][0] = *(const uint32_t*)(sA + b00 + 8);
                Al[mi][1] = *(const uint32_t*)(sA + b10 + 8);
                Al[mi][2] = *(const uint32_t*)(sA + b01 + 8);
                Al[mi][3] = *(const uint32_t*)(sA + b11 + 8);
            }
#pragma unroll
            for (int ni = 0; ni < 4; ++ni) {
                int nr = wn + ni * 8 + g;
                uint32_t bb0 = SWZ((uint32_t)(nr * 128) + oa0);
                uint32_t bb1 = SWZ((uint32_t)(nr * 128) + oa0 + 32u);
                uint32_t bh0 = *(const uint32_t*)(sB + bb0);
                uint32_t bh1 = *(const uint32_t*)(sB + bb1);
                uint32_t bl0 = *(const uint32_t*)(sB + bb0 + 8);
                uint32_t bl1 = *(const uint32_t*)(sB + bb1 + 8);
#pragma unroll
                for (int mi = 0; mi < 4; ++mi) {
                    mma16816(acc[mi][ni], Ah[mi][0], Ah[mi][1], Ah[mi][2], Ah[mi][3], bh0, bh1);
                    mma16816(acc[mi][ni], Al[mi][0], Al[mi][1], Al[mi][2], Al[mi][3], bh0, bh1);
                    mma16816(acc[mi][ni], Ah[mi][0], Ah[mi][1], Ah[mi][2], Ah[mi][3], bl0, bl1);
                }
            }
        }
        __syncthreads();
    }

    // Epilogue
#pragma unroll
    for (int mi = 0; mi < 4; ++mi) {
#pragma unroll
        for (int ni = 0; ni < 4; ++ni) {
            int r = m0 + wm + mi * 16 + g;
            int c = n0 + wn + ni * 8 + 2 * tk;
            if (mode == 0) {
                int which = c >> 8;
                int h = (c >> 5) & 7;
                int d = c & 31;
                float b0, b1;
                if (which == 0)      { b0 = q_bias[c];       b1 = q_bias[c + 1]; }
                else if (which == 2) { b0 = v_bias[c - 512]; b1 = v_bias[c - 511]; }
                else                 { b0 = 0.f; b1 = 0.f; }
                float* baseP = (which == 0) ? g_Q : (which == 1) ? g_K : g_V;
                int bw0 = r >> 6, n_0 = r & 63;
                int bw1 = (r + 8) >> 6, n_1 = (r + 8) & 63;
                float2 v0 = make_float2(acc[mi][ni][0] + b0, acc[mi][ni][1] + b1);
                float2 v1 = make_float2(acc[mi][ni][2] + b0, acc[mi][ni][3] + b1);
                *(float2*)(baseP + (size_t)((bw0 * 8 + h) * 64 + n_0) * 32 + d) = v0;
                *(float2*)(baseP + (size_t)((bw1 * 8 + h) * 64 + n_1) * 32 + d) = v1;
            } else {
                float b0 = pb[c], b1 = pb[c + 1];
                float2 v0 = make_float2(acc[mi][ni][0] + b0, acc[mi][ni][1] + b1);
                float2 v1 = make_float2(acc[mi][ni][2] + b0, acc[mi][ni][3] + b1);
                *(float2*)(out + (size_t)r * 256 + c) = v0;
                *(float2*)(out + (size_t)(r + 8) * 256 + c) = v1;
            }
        }
    }
}

// ---------------------------------------------------------------------------
// bf16 mma attention (R12/R13-proven), epilogue writes packed-split g_Os.
// CTA = 2 heads of one window (128 thr). Grid = BWIN*4.
// ---------------------------------------------------------------------------
#define ATT_HEAD_WORDS 7424
#define ATT_SMEM_BYTES (2 * ATT_HEAD_WORDS * 4)

__global__ __launch_bounds__(128) void attn_bf16(const float* __restrict__ logit_scale)
{
    extern __shared__ uint32_t smw[];
    int tid = threadIdx.x;
    int lane = tid & 31, warp = tid >> 5;
    int b = blockIdx.x >> 2;
    int h = ((blockIdx.x & 3) << 1) + (warp >> 1);
    int hp = warp >> 1;
    int wp = warp & 1;
    int wrow = wp * 32;
    int g = lane >> 2, tk = lane & 3;

    uint32_t* Qh = smw + hp * ATT_HEAD_WORDS;
    uint32_t* Ql = Qh + 1280;
    uint32_t* Kh = Ql + 1280;
    uint32_t* Kl = Kh + 1280;
    uint32_t* VTh = Kl + 1280;
    uint32_t* VTl = VTh + 1152;

    const float* Qg = g_Q + (size_t)(b * 8 + h) * 2048;
    const float* Kg = g_K + (size_t)(b * 8 + h) * 2048;
    const float* Vg = g_V + (size_t)(b * 8 + h) * 2048;

    {
        int half = lane >> 4;
        int t = lane & 15;
#pragma unroll
        for (int rr = 0; rr < 16; ++rr) {
            int r = wrow + rr * 2 + half;
            float2 qv = *(const float2*)(Qg + r * 32 + 2 * t);
            float ss = qv.x * qv.x + qv.y * qv.y;
            ss += __shfl_xor_sync(0xffffffffu, ss, 8, 16);
            ss += __shfl_xor_sync(0xffffffffu, ss, 4, 16);
            ss += __shfl_xor_sync(0xffffffffu, ss, 2, 16);
            ss += __shfl_xor_sync(0xffffffffu, ss, 1, 16);
            float inv = 1.f / fmaxf(sqrtf(ss), 1e-12f);
            uint32_t hw, lw;
            split2_bf(qv.x * inv, qv.y * inv, hw, lw);
            Qh[r * 20 + t] = hw;
            Ql[r * 20 + t] = lw;

            float2 kv = *(const float2*)(Kg + r * 32 + 2 * t);
            ss = kv.x * kv.x + kv.y * kv.y;
            ss += __shfl_xor_sync(0xffffffffu, ss, 8, 16);
            ss += __shfl_xor_sync(0xffffffffu, ss, 4, 16);
            ss += __shfl_xor_sync(0xffffffffu, ss, 2, 16);
            ss += __shfl_xor_sync(0xffffffffu, ss, 1, 16);
            inv = 1.f / fmaxf(sqrtf(ss), 1e-12f);
            split2_bf(kv.x * inv, kv.y * inv, hw, lw);
            Kh[r * 20 + t] = hw;
            Kl[r * 20 + t] = lw;
        }
#pragma unroll
        for (int i = 0; i < 16; ++i) {
            int jp = wp * 16 + i;
            float v0 = Vg[(2 * jp) * 32 + lane];
            float v1 = Vg[(2 * jp + 1) * 32 + lane];
            uint32_t hw, lw;
            split2_bf(v0, v1, hw, lw);
            VTh[lane * 36 + jp] = hw;
            VTl[lane * 36 + jp] = lw;
        }
    }
    __syncthreads();

    float sc = __expf(fminf(logit_scale[h], 4.6051701859880913f));

    float acc[2][8][4];
#pragma unroll
    for (int mi = 0; mi < 2; ++mi)
#pragma unroll
        for (int ni = 0; ni < 8; ++ni)
#pragma unroll
            for (int q = 0; q < 4; ++q) acc[mi][ni][q] = 0.f;

#pragma unroll
    for (int s = 0; s < 2; ++s) {
        int kp0 = 8 * s + tk, kp1 = kp0 + 4;
        uint32_t Ah[2][4], Al[2][4];
#pragma unroll
        for (int mi = 0; mi < 2; ++mi) {
            int r0 = wrow + mi * 16 + g;
            int r1 = r0 + 8;
            Ah[mi][0] = Qh[r0 * 20 + kp0];
            Ah[mi][1] = Qh[r1 * 20 + kp0];
            Ah[mi][2] = Qh[r0 * 20 + kp1];
            Ah[mi][3] = Qh[r1 * 20 + kp1];
            Al[mi][0] = Ql[r0 * 20 + kp0];
            Al[mi][1] = Ql[r1 * 20 + kp0];
            Al[mi][2] = Ql[r0 * 20 + kp1];
            Al[mi][3] = Ql[r1 * 20 + kp1];
        }
#pragma unroll
        for (int ni = 0; ni < 8; ++ni) {
            int n = ni * 8 + g;
            uint32_t bh0 = Kh[n * 20 + kp0];
            uint32_t bh1 = Kh[n * 20 + kp1];
            uint32_t bl0 = Kl[n * 20 + kp0];
            uint32_t bl1 = Kl[n * 20 + kp1];
#pragma unroll
            for (int mi = 0; mi < 2; ++mi) {
                mma16816(acc[mi][ni], Ah[mi][0], Ah[mi][1], Ah[mi][2], Ah[mi][3], bh0, bh1);
                mma16816(acc[mi][ni], Al[mi][0], Al[mi][1], Al[mi][2], Al[mi][3], bh0, bh1);
                mma16816(acc[mi][ni], Ah[mi][0], Ah[mi][1], Ah[mi][2], Ah[mi][3], bl0, bl1);
            }
        }
    }

    const float* bm = g_bm + (size_t)(((b & (NW - 1)) * 8 + h)) * 4096;
#pragma unroll
    for (int mi = 0; mi < 2; ++mi) {
        int rA = wrow + mi * 16 + g;
        int rB = rA + 8;
        float mxA = -1e30f, mxB = -1e30f;
#pragma unroll
        for (int ni = 0; ni < 8; ++ni) {
            int c = ni * 8 + 2 * tk;
            float2 bA = *(const float2*)(bm + rA * 64 + c);
            float2 bB = *(const float2*)(bm + rB * 64 + c);
            acc[mi][ni][0] = fmaf(sc, acc[mi][ni][0], bA.x);
            acc[mi][ni][1] = fmaf(sc, acc[mi][ni][1], bA.y);
            acc[mi][ni][2] = fmaf(sc, acc[mi][ni][2], bB.x);
            acc[mi][ni][3] = fmaf(sc, acc[mi][ni][3], bB.y);
            mxA = fmaxf(mxA, fmaxf(acc[mi][ni][0], acc[mi][ni][1]));
            mxB = fmaxf(mxB, fmaxf(acc[mi][ni][2], acc[mi][ni][3]));
        }
        mxA = fmaxf(mxA, __shfl_xor_sync(0xffffffffu, mxA, 1));
        mxA = fmaxf(mxA, __shfl_xor_sync(0xffffffffu, mxA, 2));
        mxB = fmaxf(mxB, __shfl_xor_sync(0xffffffffu, mxB, 1));
        mxB = fmaxf(mxB, __shfl_xor_sync(0xffffffffu, mxB, 2));
        float sA = 0.f, sB = 0.f;
#pragma unroll
        for (int ni = 0; ni < 8; ++ni) {
            acc[mi][ni][0] = __expf(acc[mi][ni][0] - mxA);
            acc[mi][ni][1] = __expf(acc[mi][ni][1] - mxA);
            acc[mi][ni][2] = __expf(acc[mi][ni][2] - mxB);
            acc[mi][ni][3] = __expf(acc[mi][ni][3] - mxB);
            sA += acc[mi][ni][0] + acc[mi][ni][1];
            sB += acc[mi][ni][2] + acc[mi][ni][3];
        }
        sA += __shfl_xor_sync(0xffffffffu, sA, 1);
        sA += __shfl_xor_sync(0xffffffffu, sA, 2);
        sB += __shfl_xor_sync(0xffffffffu, sB, 1);
        sB += __shfl_xor_sync(0xffffffffu, sB, 2);
        float iA = 1.f / sA, iB = 1.f / sB;
#pragma unroll
        for (int ni = 0; ni < 8; ++ni) {
            acc[mi][ni][0] *= iA;
            acc[mi][ni][1] *= iA;
            acc[mi][ni][2] *= iB;
            acc[mi][ni][3] *= iB;
        }
    }

    float o[2][4][4];
#pragma unroll
    for (int mi = 0; mi < 2; ++mi)
#pragma unroll
        for (int ni = 0; ni < 4; ++ni)
#pragma unroll
            for (int q = 0; q < 4; ++q) o[mi][ni][q] = 0.f;

#pragma unroll
    for (int s = 0; s < 4; ++s) {
        int kp0 = 8 * s + tk, kp1 = kp0 + 4;
        uint32_t vh0[4], vh1[4], vl0[4], vl1[4];
#pragma unroll
        for (int ni = 0; ni < 4; ++ni) {
            int n = ni * 8 + g;
            vh0[ni] = VTh[n * 36 + kp0];
            vh1[ni] = VTh[n * 36 + kp1];
            vl0[ni] = VTl[n * 36 + kp0];
            vl1[ni] = VTl[n * 36 + kp1];
        }
#pragma unroll
        for (int mi = 0; mi < 2; ++mi) {
            uint32_t pah[4], pal[4];
            split2_bf(acc[mi][2 * s][0],     acc[mi][2 * s][1],     pah[0], pal[0]);
            split2_bf(acc[mi][2 * s][2],     acc[mi][2 * s][3],     pah[1], pal[1]);
            split2_bf(acc[mi][2 * s + 1][0], acc[mi][2 * s + 1][1], pah[2], pal[2]);
            split2_bf(acc[mi][2 * s + 1][2], acc[mi][2 * s + 1][3], pah[3], pal[3]);
#pragma unroll
            for (int ni = 0; ni < 4; ++ni) {
                mma16816(o[mi][ni], pah[0], pah[1], pah[2], pah[3], vh0[ni], vh1[ni]);
                mma16816(o[mi][ni], pal[0], pal[1], pal[2], pal[3], vh0[ni], vh1[ni]);
                mma16816(o[mi][ni], pah[0], pah[1], pah[2], pah[3], vl0[ni], vl1[ni]);
            }
        }
    }

    // write O in packed-split layout (word row stride 256)
    uint32_t* OgW = g_Os + (size_t)(b * 64) * 256;
#pragma unroll
    for (int mi = 0; mi < 2; ++mi) {
        int r0 = wrow + mi * 16 + g;
        int r1 = r0 + 8;
#pragma unroll
        for (int ni = 0; ni < 4; ++ni) {
            uint32_t wbase = (uint32_t)((h * 4 + ni) * 8 + ((tk >> 1) << 2) + (tk & 1));
            uint32_t hw, lw;
            split2_bf(o[mi][ni][0], o[mi][ni][1], hw, lw);
            OgW[(size_t)r0 * 256 + wbase] = hw;
            OgW[(size_t)r0 * 256 + wbase + 2] = lw;
            split2_bf(o[mi][ni][2], o[mi][ni][3], hw, lw);
            OgW[(size_t)r1 * 256 + wbase] = hw;
            OgW[(size_t)r1 * 256 + wbase + 2] = lw;
        }
    }
}

// ---------------------------------------------------------------------------
extern "C" void kernel_launch(void* const* d_in, const int* in_sizes, int n_in,
                              void* d_out, int out_size)
{
    const float* x           = (const float*)d_in[0];
    const float* mask        = (const float*)d_in[1];
    const float* qkv_w       = (const float*)d_in[2];
    const float* q_bias      = (const float*)d_in[3];
    const float* v_bias      = (const float*)d_in[4];
    const float* logit_scale = (const float*)d_in[5];
    const float* cpb_w1      = (const float*)d_in[6];
    const float* cpb_b1      = (const float*)d_in[7];
    const float* cpb_w2      = (const float*)d_in[8];
    const float* proj_w      = (const float*)d_in[9];
    const float* proj_b      = (const float*)d_in[10];
    const float* coords      = (const float*)d_in[11];
    const int*   rel_idx     = (const int*)d_in[12];
    float* out = (float*)d_out;

    static int configured = 0;
    if (!configured) {
        cudaFuncSetAttribute(mma_gemm, cudaFuncAttributeMaxDynamicSharedMemorySize,
                             GSMEM_TOTAL);
        cudaFuncSetAttribute(attn_bf16, cudaFuncAttributeMaxDynamicSharedMemorySize,
                             ATT_SMEM_BYTES);
        configured = 1;
    }

    cpb_table_kernel<<<TBL, 128>>>(cpb_w1, cpb_b1, cpb_w2, coords);
    bias_gather_kernel<<<(HEADS * SEQ * SEQ + 255) / 256, 256>>>(rel_idx);
    bm_fuse_kernel<<<(NW * HEADS * SEQ * SEQ + 255) / 256, 256>>>(mask);

    {
        void* dst;
        cudaGetSymbolAddress(&dst, g_Xs);
        split_pack<<<(BWIN * SEQ * DIM / 8 + 255) / 256, 256>>>(x, (uint32_t*)dst,
                                                                BWIN * SEQ * DIM / 8);
        cudaGetSymbolAddress(&dst, g_Ws);
        split_pack<<<(3 * DIM * DIM / 8 + 255) / 256, 256>>>(qkv_w, (uint32_t*)dst,
                                                             3 * DIM * DIM / 8);
        cudaGetSymbolAddress(&dst, g_Wp);
        split_pack<<<(DIM * DIM / 8 + 255) / 256, 256>>>(proj_w, (uint32_t*)dst,
                                                         DIM * DIM / 8);
    }

    mma_gemm<<<dim3(6, 1024), 256, GSMEM_TOTAL>>>(q_bias, v_bias,
                                                  nullptr, nullptr, 0);
    attn_bf16<<<BWIN * 4, 128, ATT_SMEM_BYTES>>>(logit_scale);
    mma_gemm<<<dim3(2, 1024), 256, GSMEM_TOTAL>>>(nullptr, nullptr,
                                                  proj_b, out, 1);
}

// round 15
// speedup vs baseline: 1.1892x; 1.1892x over previous
#include <cuda_runtime.h>
#include <cuda_bf16.h>
#include <cstdint>
#include <math.h>

// Problem constants
#define BWIN   2048
#define SEQ    64
#define DIM    256
#define HEADS  8
#define HD     32
#define NW     64
#define KDIM   256
#define TBL    225
#define CPBH   512

// Scratch (device globals)
__device__ float g_Q[BWIN * HEADS * SEQ * HD];
__device__ float g_K[BWIN * HEADS * SEQ * HD];
__device__ float g_V[BWIN * HEADS * SEQ * HD];
__device__ float g_table[TBL * HEADS];
__device__ float g_bias[HEADS * SEQ * SEQ];
__device__ float g_bm[NW * HEADS * SEQ * SEQ];     // fused bias+mask

// Pre-split packed operands. Row = 256 words per 256-K row, organized as
// 8 chunks of 32 words; chunk = [hi k-pairs 0..15 (words 0-15)][lo (16-31)].
__device__ uint32_t g_Xs[(size_t)BWIN * SEQ * DIM];   // 128 MB
__device__ uint32_t g_Os[(size_t)BWIN * SEQ * DIM];   // 128 MB
__device__ uint32_t g_Ws[3 * DIM * DIM];
__device__ uint32_t g_Wp[DIM * DIM];

// SW128 swizzle on byte offsets (128B rows)
#define SWZ(b) ((b) ^ (((b) >> 3) & 0x70))

__device__ __forceinline__ uint32_t smem_u32(const void* p) {
    uint32_t a;
    asm("{ .reg .u64 t; cvta.to.shared.u64 t, %1; cvt.u32.u64 %0, t; }"
        : "=r"(a) : "l"(p));
    return a;
}

#define CP16(dst_u32, src_ptr) \
    asm volatile("cp.async.cg.shared.global [%0], [%1], 16;" \
        :: "r"(dst_u32), "l"(src_ptr) : "memory")
#define CP_COMMIT() asm volatile("cp.async.commit_group;" ::: "memory")
#define CP_WAIT0()  asm volatile("cp.async.wait_group 0;" ::: "memory")
#define CP_WAIT1()  asm volatile("cp.async.wait_group 1;" ::: "memory")

// bf16 2-level split of two floats, packed (f0 in low half)
__device__ __forceinline__ void split2_bf(float f0, float f1,
                                          uint32_t& hi, uint32_t& lo)
{
    __nv_bfloat16 h0 = __float2bfloat16_rn(f0);
    __nv_bfloat16 h1 = __float2bfloat16_rn(f1);
    float r0 = f0 - __bfloat162float(h0);
    float r1 = f1 - __bfloat162float(h1);
    __nv_bfloat16 l0 = __float2bfloat16_rn(r0);
    __nv_bfloat16 l1 = __float2bfloat16_rn(r1);
    hi = (uint32_t)__bfloat16_as_ushort(h0) | ((uint32_t)__bfloat16_as_ushort(h1) << 16);
    lo = (uint32_t)__bfloat16_as_ushort(l0) | ((uint32_t)__bfloat16_as_ushort(l1) << 16);
}

__device__ __forceinline__ void mma16816(float* c,
    uint32_t a0, uint32_t a1, uint32_t a2, uint32_t a3,
    uint32_t b0, uint32_t b1)
{
    asm volatile(
        "mma.sync.aligned.m16n8k16.row.col.f32.bf16.bf16.f32 "
        "{%0,%1,%2,%3},{%4,%5,%6,%7},{%8,%9},{%0,%1,%2,%3};"
        : "+f"(c[0]), "+f"(c[1]), "+f"(c[2]), "+f"(c[3])
        : "r"(a0), "r"(a1), "r"(a2), "r"(a3), "r"(b0), "r"(b1));
}

__device__ __forceinline__ void ldsm4(uint32_t& r0, uint32_t& r1,
                                      uint32_t& r2, uint32_t& r3, uint32_t a)
{
    asm volatile("ldmatrix.sync.aligned.m8n8.x4.shared.b16 {%0,%1,%2,%3}, [%4];"
        : "=r"(r0), "=r"(r1), "=r"(r2), "=r"(r3) : "r"(a));
}

// ---------------------------------------------------------------------------
// split_pack: fp32 -> packed layout: per 32-float chunk, hi words 0-15, lo 16-31.
// Thread handles 8 floats (granule gp of chunk).
// ---------------------------------------------------------------------------
__global__ __launch_bounds__(256) void split_pack(
    const float* __restrict__ src, uint32_t* __restrict__ dst, int n_granules)
{
    int gidx = blockIdx.x * 256 + threadIdx.x;
    if (gidx >= n_granules) return;
    int chunk = gidx >> 2, gp = gidx & 3;
    const float4* s = (const float4*)(src + (size_t)gidx * 8);
    float4 v0 = s[0], v1 = s[1];
    uint32_t h0, l0, h1, l1, h2, l2, h3, l3;
    split2_bf(v0.x, v0.y, h0, l0);
    split2_bf(v0.z, v0.w, h1, l1);
    split2_bf(v1.x, v1.y, h2, l2);
    split2_bf(v1.z, v1.w, h3, l3);
    uint32_t* drow = dst + (size_t)chunk * 32;
    *(uint4*)(drow + gp * 4) = make_uint4(h0, h1, h2, h3);
    *(uint4*)(drow + 16 + gp * 4) = make_uint4(l0, l1, l2, l3);
}

// ---------------------------------------------------------------------------
// Kernel 1: CPB MLP
// ---------------------------------------------------------------------------
__global__ __launch_bounds__(128) void cpb_table_kernel(
    const float* __restrict__ w1, const float* __restrict__ b1,
    const float* __restrict__ w2, const float* __restrict__ coords)
{
    int p = blockIdx.x;
    float c0 = coords[2 * p + 0];
    float c1 = coords[2 * p + 1];
    float acc[HEADS];
#pragma unroll
    for (int h = 0; h < HEADS; ++h) acc[h] = 0.f;

    for (int j = threadIdx.x; j < CPBH; j += 128) {
        float hid = fmaf(w1[2 * j], c0, fmaf(w1[2 * j + 1], c1, b1[j]));
        hid = fmaxf(hid, 0.f);
#pragma unroll
        for (int h = 0; h < HEADS; ++h)
            acc[h] = fmaf(hid, w2[h * CPBH + j], acc[h]);
    }
    int lane = threadIdx.x & 31, warp = threadIdx.x >> 5;
#pragma unroll
    for (int h = 0; h < HEADS; ++h)
#pragma unroll
        for (int off = 16; off; off >>= 1)
            acc[h] += __shfl_xor_sync(0xffffffffu, acc[h], off);

    __shared__ float red[4][HEADS];
    if (lane == 0)
#pragma unroll
        for (int h = 0; h < HEADS; ++h) red[warp][h] = acc[h];
    __syncthreads();
    if (threadIdx.x < HEADS) {
        float s = red[0][threadIdx.x] + red[1][threadIdx.x] +
                  red[2][threadIdx.x] + red[3][threadIdx.x];
        g_table[p * HEADS + threadIdx.x] = s;
    }
}

// ---------------------------------------------------------------------------
// Kernel 2: bias gather + 16*sigmoid
// ---------------------------------------------------------------------------
__global__ __launch_bounds__(256) void bias_gather_kernel(const int* __restrict__ rel_idx)
{
    int i = blockIdx.x * 256 + threadIdx.x;
    if (i >= HEADS * SEQ * SEQ) return;
    int h = i >> 12;
    int ij = i & 4095;
    float t = g_table[rel_idx[ij] * HEADS + h];
    g_bias[i] = 16.f / (1.f + expf(-t));
}

// ---------------------------------------------------------------------------
// Kernel 2b: fuse bias[h] + mask[w] -> g_bm[w][h][ij]
// ---------------------------------------------------------------------------
__global__ __launch_bounds__(256) void bm_fuse_kernel(const float* __restrict__ mask)
{
    int i = blockIdx.x * 256 + threadIdx.x;
    if (i >= NW * HEADS * SEQ * SEQ) return;
    int wh = i >> 12;
    int ij = i & 4095;
    int w = wh >> 3, h = wh & 7;
    g_bm[i] = g_bias[h * 4096 + ij] + mask[w * 4096 + ij];
}

// ---------------------------------------------------------------------------
// 3-term bf16 mma.sync GEMM with ldmatrix fragment loads.
// 128 threads (4 warps, 64x64 tiles), pre-split operands, cp.async dbuf.
// CTA 128x128, BK=32, K=256 (8 stages). smem 2 x (A 16KB + B 16KB) = 64KB.
// smem row (128B, SW128 on 16B chunks): bytes 0-63 hi k0..31, 64-127 lo.
// ---------------------------------------------------------------------------
#define GSMEM_TOTAL 65536

__global__ __launch_bounds__(128, 2) void mma_gemm(
    const float* __restrict__ q_bias, const float* __restrict__ v_bias,
    const float* __restrict__ pb, float* __restrict__ out, int mode)
{
    extern __shared__ char sm[];
    uint32_t sb = smem_u32(sm);
    const uint32_t* As = (mode == 0) ? g_Xs : g_Os;
    const uint32_t* Bsrc = (mode == 0) ? g_Ws : g_Wp;
    int tid = threadIdx.x;
    int lane = tid & 31, warp = tid >> 5;
    int m0 = blockIdx.y * 128;
    int n0 = blockIdx.x * 128;
    int wm = (warp >> 1) * 64;
    int wn = (warp & 1) * 64;

    float acc[4][8][4];
#pragma unroll
    for (int mi = 0; mi < 4; ++mi)
#pragma unroll
        for (int ni = 0; ni < 8; ++ni)
#pragma unroll
            for (int q = 0; q < 4; ++q) acc[mi][ni][q] = 0.f;

    int g = lane >> 2;       // 0..7
    int tk = lane & 3;       // 0..3

    // ldmatrix address components (per thread, constant over k loop)
    int a_row_l = lane & 15;                 // A: row within 16
    uint32_t a_cb16 = ((lane >> 4) & 1) * 16u;   // A: 16B half select
    int b_nrow_l = ((lane >> 4) & 1) * 8 + (lane & 7);  // B: n-row within 16
    uint32_t b_cb16 = ((lane >> 3) & 1) * 16u;   // B: 16B half select

#define ISSUE_STAGE(c) do { \
    uint32_t dbuf = sb + (uint32_t)(((c) & 1) * 32768); \
    const uint32_t* arow = As + (size_t)(m0 + tid) * 256 + (c) * 32; \
    const uint32_t* brow = Bsrc + (size_t)(n0 + tid) * 256 + (c) * 32; \
    _Pragma("unroll") \
    for (int gp = 0; gp < 4; ++gp) { \
        uint32_t o_ = (uint32_t)(tid * 128 + gp * 32); \
        CP16(dbuf + SWZ(o_), arow + gp * 8); \
        CP16(dbuf + SWZ(o_ + 16u), arow + gp * 8 + 4); \
        CP16(dbuf + 16384u + SWZ(o_), brow + gp * 8); \
        CP16(dbuf + 16384u + SWZ(o_ + 16u), brow + gp * 8 + 4); \
    } \
    CP_COMMIT(); \
} while (0)

    ISSUE_STAGE(0);

    for (int c = 0; c < 8; ++c) {
        if (c < 7) { ISSUE_STAGE(c + 1); CP_WAIT1(); }
        else       { CP_WAIT0(); }
        __syncthreads();

        uint32_t sAb = sb + (uint32_t)((c & 1) * 32768);
        uint32_t sBb = sAb + 16384u;
#pragma unroll
        for (int s = 0; s < 2; ++s) {
            uint32_t Ah[4][4], Al[4][4];
#pragma unroll
            for (int mi = 0; mi < 4; ++mi) {
                int row = wm + mi * 16 + a_row_l;
                uint32_t xr = ((uint32_t)(row & 7)) << 4;
                uint32_t cb = ((uint32_t)(32 * s) + a_cb16) ^ xr;
                uint32_t addr = sAb + (uint32_t)(row * 128) + cb;
                ldsm4(Ah[mi][0], Ah[mi][1], Ah[mi][2], Ah[mi][3], addr);
                uint32_t addrl = sAb + (uint32_t)(row * 128) + (cb ^ 64u);
                ldsm4(Al[mi][0], Al[mi][1], Al[mi][2], Al[mi][3], addrl);
            }
#pragma unroll
            for (int p = 0; p < 4; ++p) {
                int nrow = wn + p * 16 + b_nrow_l;
                uint32_t xr = ((uint32_t)(nrow & 7)) << 4;
                uint32_t cb = ((uint32_t)(32 * s) + b_cb16) ^ xr;
                uint32_t baddr = sBb + (uint32_t)(nrow * 128) + cb;
                uint32_t bh0, bh1, bh2, bh3, bl0, bl1, bl2, bl3;
                ldsm4(bh0, bh1, bh2, bh3, baddr);
                uint32_t baddl = sBb + (uint32_t)(nrow * 128) + (cb ^ 64u);
                ldsm4(bl0, bl1, bl2, bl3, baddl);
#pragma unroll
                for (int mi = 0; mi < 4; ++mi) {
                    mma16816(acc[mi][2 * p], Ah[mi][0], Ah[mi][1], Ah[mi][2], Ah[mi][3], bh0, bh1);
                    mma16816(acc[mi][2 * p], Al[mi][0], Al[mi][1], Al[mi][2], Al[mi][3], bh0, bh1);
                    mma16816(acc[mi][2 * p], Ah[mi][0], Ah[mi][1], Ah[mi][2], Ah[mi][3], bl0, bl1);
                }
#pragma unroll
                for (int mi = 0; mi < 4; ++mi) {
                    mma16816(acc[mi][2 * p + 1], Ah[mi][0], Ah[mi][1], Ah[mi][2], Ah[mi][3], bh2, bh3);
                    mma16816(acc[mi][2 * p + 1], Al[mi][0], Al[mi][1], Al[mi][2], Al[mi][3], bh2, bh3);
                    mma16816(acc[mi][2 * p + 1], Ah[mi][0], Ah[mi][1], Ah[mi][2], Ah[mi][3], bl2, bl3);
                }
            }
        }
        __syncthreads();
    }

    // Epilogue
#pragma unroll
    for (int mi = 0; mi < 4; ++mi) {
#pragma unroll
        for (int ni = 0; ni < 8; ++ni) {
            int r = m0 + wm + mi * 16 + g;
            int c = n0 + wn + ni * 8 + 2 * tk;
            if (mode == 0) {
                int which = c >> 8;
                int h = (c >> 5) & 7;
                int d = c & 31;
                float b0, b1;
                if (which == 0)      { b0 = q_bias[c];       b1 = q_bias[c + 1]; }
                else if (which == 2) { b0 = v_bias[c - 512]; b1 = v_bias[c - 511]; }
                else                 { b0 = 0.f; b1 = 0.f; }
                float* baseP = (which == 0) ? g_Q : (which == 1) ? g_K : g_V;
                int bw0 = r >> 6, n_0 = r & 63;
                int bw1 = (r + 8) >> 6, n_1 = (r + 8) & 63;
                float2 v0 = make_float2(acc[mi][ni][0] + b0, acc[mi][ni][1] + b1);
                float2 v1 = make_float2(acc[mi][ni][2] + b0, acc[mi][ni][3] + b1);
                *(float2*)(baseP + (size_t)((bw0 * 8 + h) * 64 + n_0) * 32 + d) = v0;
                *(float2*)(baseP + (size_t)((bw1 * 8 + h) * 64 + n_1) * 32 + d) = v1;
            } else {
                float b0 = pb[c], b1 = pb[c + 1];
                float2 v0 = make_float2(acc[mi][ni][0] + b0, acc[mi][ni][1] + b1);
                float2 v1 = make_float2(acc[mi][ni][2] + b0, acc[mi][ni][3] + b1);
                *(float2*)(out + (size_t)r * 256 + c) = v0;
                *(float2*)(out + (size_t)(r + 8) * 256 + c) = v1;
            }
        }
    }
}

// ---------------------------------------------------------------------------
// bf16 mma attention (R12-proven), epilogue writes packed-split g_Os
// in the NEW layout (chunk = h; hi word h*32 + kp, lo word h*32 + 16 + kp).
// CTA = 2 heads of one window (128 thr). Grid = BWIN*4.
// ---------------------------------------------------------------------------
#define ATT_HEAD_WORDS 7424
#define ATT_SMEM_BYTES (2 * ATT_HEAD_WORDS * 4)

__global__ __launch_bounds__(128) void attn_bf16(const float* __restrict__ logit_scale)
{
    extern __shared__ uint32_t smw[];
    int tid = threadIdx.x;
    int lane = tid & 31, warp = tid >> 5;
    int b = blockIdx.x >> 2;
    int h = ((blockIdx.x & 3) << 1) + (warp >> 1);
    int hp = warp >> 1;
    int wp = warp & 1;
    int wrow = wp * 32;
    int g = lane >> 2, tk = lane & 3;

    uint32_t* Qh = smw + hp * ATT_HEAD_WORDS;
    uint32_t* Ql = Qh + 1280;
    uint32_t* Kh = Ql + 1280;
    uint32_t* Kl = Kh + 1280;
    uint32_t* VTh = Kl + 1280;
    uint32_t* VTl = VTh + 1152;

    const float* Qg = g_Q + (size_t)(b * 8 + h) * 2048;
    const float* Kg = g_K + (size_t)(b * 8 + h) * 2048;
    const float* Vg = g_V + (size_t)(b * 8 + h) * 2048;

    {
        int half = lane >> 4;
        int t = lane & 15;
#pragma unroll
        for (int rr = 0; rr < 16; ++rr) {
            int r = wrow + rr * 2 + half;
            float2 qv = *(const float2*)(Qg + r * 32 + 2 * t);
            float ss = qv.x * qv.x + qv.y * qv.y;
            ss += __shfl_xor_sync(0xffffffffu, ss, 8, 16);
            ss += __shfl_xor_sync(0xffffffffu, ss, 4, 16);
            ss += __shfl_xor_sync(0xffffffffu, ss, 2, 16);
            ss += __shfl_xor_sync(0xffffffffu, ss, 1, 16);
            float inv = 1.f / fmaxf(sqrtf(ss), 1e-12f);
            uint32_t hw, lw;
            split2_bf(qv.x * inv, qv.y * inv, hw, lw);
            Qh[r * 20 + t] = hw;
            Ql[r * 20 + t] = lw;

            float2 kv = *(const float2*)(Kg + r * 32 + 2 * t);
            ss = kv.x * kv.x + kv.y * kv.y;
            ss += __shfl_xor_sync(0xffffffffu, ss, 8, 16);
            ss += __shfl_xor_sync(0xffffffffu, ss, 4, 16);
            ss += __shfl_xor_sync(0xffffffffu, ss, 2, 16);
            ss += __shfl_xor_sync(0xffffffffu, ss, 1, 16);
            inv = 1.f / fmaxf(sqrtf(ss), 1e-12f);
            split2_bf(kv.x * inv, kv.y * inv, hw, lw);
            Kh[r * 20 + t] = hw;
            Kl[r * 20 + t] = lw;
        }
#pragma unroll
        for (int i = 0; i < 16; ++i) {
            int jp = wp * 16 + i;
            float v0 = Vg[(2 * jp) * 32 + lane];
            float v1 = Vg[(2 * jp + 1) * 32 + lane];
            uint32_t hw, lw;
            split2_bf(v0, v1, hw, lw);
            VTh[lane * 36 + jp] = hw;
            VTl[lane * 36 + jp] = lw;
        }
    }
    __syncthreads();

    float sc = __expf(fminf(logit_scale[h], 4.6051701859880913f));

    float acc[2][8][4];
#pragma unroll
    for (int mi = 0; mi < 2; ++mi)
#pragma unroll
        for (int ni = 0; ni < 8; ++ni)
#pragma unroll
            for (int q = 0; q < 4; ++q) acc[mi][ni][q] = 0.f;

#pragma unroll
    for (int s = 0; s < 2; ++s) {
        int kp0 = 8 * s + tk, kp1 = kp0 + 4;
        uint32_t Ah[2][4], Al[2][4];
#pragma unroll
        for (int mi = 0; mi < 2; ++mi) {
            int r0 = wrow + mi * 16 + g;
            int r1 = r0 + 8;
            Ah[mi][0] = Qh[r0 * 20 + kp0];
            Ah[mi][1] = Qh[r1 * 20 + kp0];
            Ah[mi][2] = Qh[r0 * 20 + kp1];
            Ah[mi][3] = Qh[r1 * 20 + kp1];
            Al[mi][0] = Ql[r0 * 20 + kp0];
            Al[mi][1] = Ql[r1 * 20 + kp0];
            Al[mi][2] = Ql[r0 * 20 + kp1];
            Al[mi][3] = Ql[r1 * 20 + kp1];
        }
#pragma unroll
        for (int ni = 0; ni < 8; ++ni) {
            int n = ni * 8 + g;
            uint32_t bh0 = Kh[n * 20 + kp0];
            uint32_t bh1 = Kh[n * 20 + kp1];
            uint32_t bl0 = Kl[n * 20 + kp0];
            uint32_t bl1 = Kl[n * 20 + kp1];
#pragma unroll
            for (int mi = 0; mi < 2; ++mi) {
                mma16816(acc[mi][ni], Ah[mi][0], Ah[mi][1], Ah[mi][2], Ah[mi][3], bh0, bh1);
                mma16816(acc[mi][ni], Al[mi][0], Al[mi][1], Al[mi][2], Al[mi][3], bh0, bh1);
                mma16816(acc[mi][ni], Ah[mi][0], Ah[mi][1], Ah[mi][2], Ah[mi][3], bl0, bl1);
            }
        }
    }

    const float* bm = g_bm + (size_t)(((b & (NW - 1)) * 8 + h)) * 4096;
#pragma unroll
    for (int mi = 0; mi < 2; ++mi) {
        int rA = wrow + mi * 16 + g;
        int rB = rA + 8;
        float mxA = -1e30f, mxB = -1e30f;
#pragma unroll
        for (int ni = 0; ni < 8; ++ni) {
            int c = ni * 8 + 2 * tk;
            float2 bA = *(const float2*)(bm + rA * 64 + c);
            float2 bB = *(const float2*)(bm + rB * 64 + c);
            acc[mi][ni][0] = fmaf(sc, acc[mi][ni][0], bA.x);
            acc[mi][ni][1] = fmaf(sc, acc[mi][ni][1], bA.y);
            acc[mi][ni][2] = fmaf(sc, acc[mi][ni][2], bB.x);
            acc[mi][ni][3] = fmaf(sc, acc[mi][ni][3], bB.y);
            mxA = fmaxf(mxA, fmaxf(acc[mi][ni][0], acc[mi][ni][1]));
            mxB = fmaxf(mxB, fmaxf(acc[mi][ni][2], acc[mi][ni][3]));
        }
        mxA = fmaxf(mxA, __shfl_xor_sync(0xffffffffu, mxA, 1));
        mxA = fmaxf(mxA, __shfl_xor_sync(0xffffffffu, mxA, 2));
        mxB = fmaxf(mxB, __shfl_xor_sync(0xffffffffu, mxB, 1));
        mxB = fmaxf(mxB, __shfl_xor_sync(0xffffffffu, mxB, 2));
        float sA = 0.f, sB = 0.f;
#pragma unroll
        for (int ni = 0; ni < 8; ++ni) {
            acc[mi][ni][0] = __expf(acc[mi][ni][0] - mxA);
            acc[mi][ni][1] = __expf(acc[mi][ni][1] - mxA);
            acc[mi][ni][2] = __expf(acc[mi][ni][2] - mxB);
            acc[mi][ni][3] = __expf(acc[mi][ni][3] - mxB);
            sA += acc[mi][ni][0] + acc[mi][ni][1];
            sB += acc[mi][ni][2] + acc[mi][ni][3];
        }
        sA += __shfl_xor_sync(0xffffffffu, sA, 1);
        sA += __shfl_xor_sync(0xffffffffu, sA, 2);
        sB += __shfl_xor_sync(0xffffffffu, sB, 1);
        sB += __shfl_xor_sync(0xffffffffu, sB, 2);
        float iA = 1.f / sA, iB = 1.f / sB;
#pragma unroll
        for (int ni = 0; ni < 8; ++ni) {
            acc[mi][ni][0] *= iA;
            acc[mi][ni][1] *= iA;
            acc[mi][ni][2] *= iB;
            acc[mi][ni][3] *= iB;
        }
    }

    float o[2][4][4];
#pragma unroll
    for (int mi = 0; mi < 2; ++mi)
#pragma unroll
        for (int ni = 0; ni < 4; ++ni)
#pragma unroll
            for (int q = 0; q < 4; ++q) o[mi][ni][q] = 0.f;

#pragma unroll
    for (int s = 0; s < 4; ++s) {
        int kp0 = 8 * s + tk, kp1 = kp0 + 4;
        uint32_t vh0[4], vh1[4], vl0[4], vl1[4];
#pragma unroll
        for (int ni = 0; ni < 4; ++ni) {
            int n = ni * 8 + g;
            vh0[ni] = VTh[n * 36 + kp0];
            vh1[ni] = VTh[n * 36 + kp1];
            vl0[ni] = VTl[n * 36 + kp0];
            vl1[ni] = VTl[n * 36 + kp1];
        }
#pragma unroll
        for (int mi = 0; mi < 2; ++mi) {
            uint32_t pah[4], pal[4];
            split2_bf(acc[mi][2 * s][0],     acc[mi][2 * s][1],     pah[0], pal[0]);
            split2_bf(acc[mi][2 * s][2],     acc[mi][2 * s][3],     pah[1], pal[1]);
            split2_bf(acc[mi][2 * s + 1][0], acc[mi][2 * s + 1][1], pah[2], pal[2]);
            split2_bf(acc[mi][2 * s + 1][2], acc[mi][2 * s + 1][3], pah[3], pal[3]);
#pragma unroll
            for (int ni = 0; ni < 4; ++ni) {
                mma16816(o[mi][ni], pah[0], pah[1], pah[2], pah[3], vh0[ni], vh1[ni]);
                mma16816(o[mi][ni], pal[0], pal[1], pal[2], pal[3], vh0[ni], vh1[ni]);
                mma16816(o[mi][ni], pah[0], pah[1], pah[2], pah[3], vl0[ni], vl1[ni]);
            }
        }
    }

    // write O in NEW packed layout: chunk h, hi word h*32 + kp, lo +16.
    uint32_t* OgW = g_Os + (size_t)(b * 64) * 256;
#pragma unroll
    for (int mi = 0; mi < 2; ++mi) {
        int r0 = wrow + mi * 16 + g;
        int r1 = r0 + 8;
#pragma unroll
        for (int ni = 0; ni < 4; ++ni) {
            uint32_t wbase = (uint32_t)(h * 32 + ni * 4 + tk);
            uint32_t hw, lw;
            split2_bf(o[mi][ni][0], o[mi][ni][1], hw, lw);
            OgW[(size_t)r0 * 256 + wbase] = hw;
            OgW[(size_t)r0 * 256 + wbase + 16] = lw;
            split2_bf(o[mi][ni][2], o[mi][ni][3], hw, lw);
            OgW[(size_t)r1 * 256 + wbase] = hw;
            OgW[(size_t)r1 * 256 + wbase + 16] = lw;
        }
    }
}

// ---------------------------------------------------------------------------
extern "C" void kernel_launch(void* const* d_in, const int* in_sizes, int n_in,
                              void* d_out, int out_size)
{
    const float* x           = (const float*)d_in[0];
    const float* mask        = (const float*)d_in[1];
    const float* qkv_w       = (const float*)d_in[2];
    const float* q_bias      = (const float*)d_in[3];
    const float* v_bias      = (const float*)d_in[4];
    const float* logit_scale = (const float*)d_in[5];
    const float* cpb_w1      = (const float*)d_in[6];
    const float* cpb_b1      = (const float*)d_in[7];
    const float* cpb_w2      = (const float*)d_in[8];
    const float* proj_w      = (const float*)d_in[9];
    const float* proj_b      = (const float*)d_in[10];
    const float* coords      = (const float*)d_in[11];
    const int*   rel_idx     = (const int*)d_in[12];
    float* out = (float*)d_out;

    static int configured = 0;
    if (!configured) {
        cudaFuncSetAttribute(mma_gemm, cudaFuncAttributeMaxDynamicSharedMemorySize,
                             GSMEM_TOTAL);
        cudaFuncSetAttribute(attn_bf16, cudaFuncAttributeMaxDynamicSharedMemorySize,
                             ATT_SMEM_BYTES);
        configured = 1;
    }

    cpb_table_kernel<<<TBL, 128>>>(cpb_w1, cpb_b1, cpb_w2, coords);
    bias_gather_kernel<<<(HEADS * SEQ * SEQ + 255) / 256, 256>>>(rel_idx);
    bm_fuse_kernel<<<(NW * HEADS * SEQ * SEQ + 255) / 256, 256>>>(mask);

    {
        void* dst;
        cudaGetSymbolAddress(&dst, g_Xs);
        split_pack<<<(BWIN * SEQ * DIM / 8 + 255) / 256, 256>>>(x, (uint32_t*)dst,
                                                                BWIN * SEQ * DIM / 8);
        cudaGetSymbolAddress(&dst, g_Ws);
        split_pack<<<(3 * DIM * DIM / 8 + 255) / 256, 256>>>(qkv_w, (uint32_t*)dst,
                                                             3 * DIM * DIM / 8);
        cudaGetSymbolAddress(&dst, g_Wp);
        split_pack<<<(DIM * DIM / 8 + 255) / 256, 256>>>(proj_w, (uint32_t*)dst,
                                                         DIM * DIM / 8);
    }

    mma_gemm<<<dim3(6, 1024), 128, GSMEM_TOTAL>>>(q_bias, v_bias,
                                                  nullptr, nullptr, 0);
    attn_bf16<<<BWIN * 4, 128, ATT_SMEM_BYTES>>>(logit_scale);
    mma_gemm<<<dim3(2, 1024), 128, GSMEM_TOTAL>>>(nullptr, nullptr,
                                                  proj_b, out, 1);
}

// round 16
// speedup vs baseline: 1.5112x; 1.2708x over previous
#include <cuda_runtime.h>
#include <cuda_bf16.h>
#include <cstdint>
#include <math.h>

// Problem constants
#define BWIN   2048
#define SEQ    64
#define DIM    256
#define HEADS  8
#define HD     32
#define NW     64
#define KDIM   256
#define TBL    225
#define CPBH   512

// Scratch (device globals)
__device__ float g_V[BWIN * HEADS * SEQ * HD];
__device__ float g_table[TBL * HEADS];
__device__ float g_bias[HEADS * SEQ * SEQ];
__device__ float g_bm[NW * HEADS * SEQ * SEQ];     // fused bias+mask

// Pre-split packed operands. GEMM inputs: per 256-K row, 8 chunks of 32 words,
// chunk = [hi k-pairs 0..15][lo 16..31].
__device__ uint32_t g_Xs[(size_t)BWIN * SEQ * DIM];   // 128 MB
__device__ uint32_t g_Os[(size_t)BWIN * SEQ * DIM];   // 128 MB
__device__ uint32_t g_Ws[3 * DIM * DIM];
__device__ uint32_t g_Wp[DIM * DIM];
// Pre-normalized, pre-split Q/K: per (b,h): 64 rows x 32 words [hi16|lo16]
__device__ uint32_t g_Qs2[(size_t)BWIN * HEADS * SEQ * 32];   // 134 MB
__device__ uint32_t g_Ks2[(size_t)BWIN * HEADS * SEQ * 32];   // 134 MB

// SW128 swizzle on byte offsets (128B rows)
#define SWZ(b) ((b) ^ (((b) >> 3) & 0x70))

__device__ __forceinline__ uint32_t smem_u32(const void* p) {
    uint32_t a;
    asm("{ .reg .u64 t; cvta.to.shared.u64 t, %1; cvt.u32.u64 %0, t; }"
        : "=r"(a) : "l"(p));
    return a;
}

#define CP16(dst_u32, src_ptr) \
    asm volatile("cp.async.cg.shared.global [%0], [%1], 16;" \
        :: "r"(dst_u32), "l"(src_ptr) : "memory")
#define CP_COMMIT() asm volatile("cp.async.commit_group;" ::: "memory")
#define CP_WAIT0()  asm volatile("cp.async.wait_group 0;" ::: "memory")
#define CP_WAIT1()  asm volatile("cp.async.wait_group 1;" ::: "memory")

// bf16 2-level split of two floats, packed (f0 in low half)
__device__ __forceinline__ void split2_bf(float f0, float f1,
                                          uint32_t& hi, uint32_t& lo)
{
    __nv_bfloat16 h0 = __float2bfloat16_rn(f0);
    __nv_bfloat16 h1 = __float2bfloat16_rn(f1);
    float r0 = f0 - __bfloat162float(h0);
    float r1 = f1 - __bfloat162float(h1);
    __nv_bfloat16 l0 = __float2bfloat16_rn(r0);
    __nv_bfloat16 l1 = __float2bfloat16_rn(r1);
    hi = (uint32_t)__bfloat16_as_ushort(h0) | ((uint32_t)__bfloat16_as_ushort(h1) << 16);
    lo = (uint32_t)__bfloat16_as_ushort(l0) | ((uint32_t)__bfloat16_as_ushort(l1) << 16);
}

__device__ __forceinline__ void mma16816(float* c,
    uint32_t a0, uint32_t a1, uint32_t a2, uint32_t a3,
    uint32_t b0, uint32_t b1)
{
    asm volatile(
        "mma.sync.aligned.m16n8k16.row.col.f32.bf16.bf16.f32 "
        "{%0,%1,%2,%3},{%4,%5,%6,%7},{%8,%9},{%0,%1,%2,%3};"
        : "+f"(c[0]), "+f"(c[1]), "+f"(c[2]), "+f"(c[3])
        : "r"(a0), "r"(a1), "r"(a2), "r"(a3), "r"(b0), "r"(b1));
}

__device__ __forceinline__ void ldsm4(uint32_t& r0, uint32_t& r1,
                                      uint32_t& r2, uint32_t& r3, uint32_t a)
{
    asm volatile("ldmatrix.sync.aligned.m8n8.x4.shared.b16 {%0,%1,%2,%3}, [%4];"
        : "=r"(r0), "=r"(r1), "=r"(r2), "=r"(r3) : "r"(a));
}

// ---------------------------------------------------------------------------
// split_pack: fp32 -> packed layout: per 32-float chunk, hi words 0-15, lo 16-31.
// ---------------------------------------------------------------------------
__global__ __launch_bounds__(256) void split_pack(
    const float* __restrict__ src, uint32_t* __restrict__ dst, int n_granules)
{
    int gidx = blockIdx.x * 256 + threadIdx.x;
    if (gidx >= n_granules) return;
    int chunk = gidx >> 2, gp = gidx & 3;
    const float4* s = (const float4*)(src + (size_t)gidx * 8);
    float4 v0 = s[0], v1 = s[1];
    uint32_t h0, l0, h1, l1, h2, l2, h3, l3;
    split2_bf(v0.x, v0.y, h0, l0);
    split2_bf(v0.z, v0.w, h1, l1);
    split2_bf(v1.x, v1.y, h2, l2);
    split2_bf(v1.z, v1.w, h3, l3);
    uint32_t* drow = dst + (size_t)chunk * 32;
    *(uint4*)(drow + gp * 4) = make_uint4(h0, h1, h2, h3);
    *(uint4*)(drow + 16 + gp * 4) = make_uint4(l0, l1, l2, l3);
}

// ---------------------------------------------------------------------------
// Kernel 1: CPB MLP
// ---------------------------------------------------------------------------
__global__ __launch_bounds__(128) void cpb_table_kernel(
    const float* __restrict__ w1, const float* __restrict__ b1,
    const float* __restrict__ w2, const float* __restrict__ coords)
{
    int p = blockIdx.x;
    float c0 = coords[2 * p + 0];
    float c1 = coords[2 * p + 1];
    float acc[HEADS];
#pragma unroll
    for (int h = 0; h < HEADS; ++h) acc[h] = 0.f;

    for (int j = threadIdx.x; j < CPBH; j += 128) {
        float hid = fmaf(w1[2 * j], c0, fmaf(w1[2 * j + 1], c1, b1[j]));
        hid = fmaxf(hid, 0.f);
#pragma unroll
        for (int h = 0; h < HEADS; ++h)
            acc[h] = fmaf(hid, w2[h * CPBH + j], acc[h]);
    }
    int lane = threadIdx.x & 31, warp = threadIdx.x >> 5;
#pragma unroll
    for (int h = 0; h < HEADS; ++h)
#pragma unroll
        for (int off = 16; off; off >>= 1)
            acc[h] += __shfl_xor_sync(0xffffffffu, acc[h], off);

    __shared__ float red[4][HEADS];
    if (lane == 0)
#pragma unroll
        for (int h = 0; h < HEADS; ++h) red[warp][h] = acc[h];
    __syncthreads();
    if (threadIdx.x < HEADS) {
        float s = red[0][threadIdx.x] + red[1][threadIdx.x] +
                  red[2][threadIdx.x] + red[3][threadIdx.x];
        g_table[p * HEADS + threadIdx.x] = s;
    }
}

// ---------------------------------------------------------------------------
// Kernel 2: bias gather + 16*sigmoid
// ---------------------------------------------------------------------------
__global__ __launch_bounds__(256) void bias_gather_kernel(const int* __restrict__ rel_idx)
{
    int i = blockIdx.x * 256 + threadIdx.x;
    if (i >= HEADS * SEQ * SEQ) return;
    int h = i >> 12;
    int ij = i & 4095;
    float t = g_table[rel_idx[ij] * HEADS + h];
    g_bias[i] = 16.f / (1.f + expf(-t));
}

// ---------------------------------------------------------------------------
// Kernel 2b: fuse bias[h] + mask[w] -> g_bm[w][h][ij]
// ---------------------------------------------------------------------------
__global__ __launch_bounds__(256) void bm_fuse_kernel(const float* __restrict__ mask)
{
    int i = blockIdx.x * 256 + threadIdx.x;
    if (i >= NW * HEADS * SEQ * SEQ) return;
    int wh = i >> 12;
    int ij = i & 4095;
    int w = wh >> 3, h = wh & 7;
    g_bm[i] = g_bias[h * 4096 + ij] + mask[w * 4096 + ij];
}

// ---------------------------------------------------------------------------
// 3-term bf16 mma.sync GEMM with ldmatrix fragment loads (R15-proven).
// mode 0 epilogue: Q/K blocks get L2-normalized + split + packed to g_Qs2/g_Ks2;
// V blocks write fp32 g_V.
// ---------------------------------------------------------------------------
#define GSMEM_TOTAL 65536

__global__ __launch_bounds__(128, 2) void mma_gemm(
    const float* __restrict__ q_bias, const float* __restrict__ v_bias,
    const float* __restrict__ pb, float* __restrict__ out, int mode)
{
    extern __shared__ char sm[];
    uint32_t sb = smem_u32(sm);
    const uint32_t* As = (mode == 0) ? g_Xs : g_Os;
    const uint32_t* Bsrc = (mode == 0) ? g_Ws : g_Wp;
    int tid = threadIdx.x;
    int lane = tid & 31, warp = tid >> 5;
    int m0 = blockIdx.y * 128;
    int n0 = blockIdx.x * 128;
    int wm = (warp >> 1) * 64;
    int wn = (warp & 1) * 64;

    float acc[4][8][4];
#pragma unroll
    for (int mi = 0; mi < 4; ++mi)
#pragma unroll
        for (int ni = 0; ni < 8; ++ni)
#pragma unroll
            for (int q = 0; q < 4; ++q) acc[mi][ni][q] = 0.f;

    int g = lane >> 2;       // 0..7
    int tk = lane & 3;       // 0..3

    int a_row_l = lane & 15;
    uint32_t a_cb16 = ((lane >> 4) & 1) * 16u;
    int b_nrow_l = ((lane >> 4) & 1) * 8 + (lane & 7);
    uint32_t b_cb16 = ((lane >> 3) & 1) * 16u;

#define ISSUE_STAGE(c) do { \
    uint32_t dbuf = sb + (uint32_t)(((c) & 1) * 32768); \
    const uint32_t* arow = As + (size_t)(m0 + tid) * 256 + (c) * 32; \
    const uint32_t* brow = Bsrc + (size_t)(n0 + tid) * 256 + (c) * 32; \
    _Pragma("unroll") \
    for (int gp = 0; gp < 4; ++gp) { \
        uint32_t o_ = (uint32_t)(tid * 128 + gp * 32); \
        CP16(dbuf + SWZ(o_), arow + gp * 8); \
        CP16(dbuf + SWZ(o_ + 16u), arow + gp * 8 + 4); \
        CP16(dbuf + 16384u + SWZ(o_), brow + gp * 8); \
        CP16(dbuf + 16384u + SWZ(o_ + 16u), brow + gp * 8 + 4); \
    } \
    CP_COMMIT(); \
} while (0)

    ISSUE_STAGE(0);

    for (int c = 0; c < 8; ++c) {
        if (c < 7) { ISSUE_STAGE(c + 1); CP_WAIT1(); }
        else       { CP_WAIT0(); }
        __syncthreads();

        uint32_t sAb = sb + (uint32_t)((c & 1) * 32768);
        uint32_t sBb = sAb + 16384u;
#pragma unroll
        for (int s = 0; s < 2; ++s) {
            uint32_t Ah[4][4], Al[4][4];
#pragma unroll
            for (int mi = 0; mi < 4; ++mi) {
                int row = wm + mi * 16 + a_row_l;
                uint32_t xr = ((uint32_t)(row & 7)) << 4;
                uint32_t cb = ((uint32_t)(32 * s) + a_cb16) ^ xr;
                uint32_t addr = sAb + (uint32_t)(row * 128) + cb;
                ldsm4(Ah[mi][0], Ah[mi][1], Ah[mi][2], Ah[mi][3], addr);
                uint32_t addrl = sAb + (uint32_t)(row * 128) + (cb ^ 64u);
                ldsm4(Al[mi][0], Al[mi][1], Al[mi][2], Al[mi][3], addrl);
            }
#pragma unroll
            for (int p = 0; p < 4; ++p) {
                int nrow = wn + p * 16 + b_nrow_l;
                uint32_t xr = ((uint32_t)(nrow & 7)) << 4;
                uint32_t cb = ((uint32_t)(32 * s) + b_cb16) ^ xr;
                uint32_t baddr = sBb + (uint32_t)(nrow * 128) + cb;
                uint32_t bh0, bh1, bh2, bh3, bl0, bl1, bl2, bl3;
                ldsm4(bh0, bh1, bh2, bh3, baddr);
                uint32_t baddl = sBb + (uint32_t)(nrow * 128) + (cb ^ 64u);
                ldsm4(bl0, bl1, bl2, bl3, baddl);
#pragma unroll
                for (int mi = 0; mi < 4; ++mi) {
                    mma16816(acc[mi][2 * p], Ah[mi][0], Ah[mi][1], Ah[mi][2], Ah[mi][3], bh0, bh1);
                    mma16816(acc[mi][2 * p], Al[mi][0], Al[mi][1], Al[mi][2], Al[mi][3], bh0, bh1);
                    mma16816(acc[mi][2 * p], Ah[mi][0], Ah[mi][1], Ah[mi][2], Ah[mi][3], bl0, bl1);
                }
#pragma unroll
                for (int mi = 0; mi < 4; ++mi) {
                    mma16816(acc[mi][2 * p + 1], Ah[mi][0], Ah[mi][1], Ah[mi][2], Ah[mi][3], bh2, bh3);
                    mma16816(acc[mi][2 * p + 1], Al[mi][0], Al[mi][1], Al[mi][2], Al[mi][3], bh2, bh3);
                    mma16816(acc[mi][2 * p + 1], Ah[mi][0], Ah[mi][1], Ah[mi][2], Ah[mi][3], bl2, bl3);
                }
            }
        }
        __syncthreads();
    }

    // Epilogue
    if (mode == 0) {
        int which = (n0 + wn) >> 8;   // 0=Q, 1=K, 2=V (uniform over warp)
        if (which == 2) {
#pragma unroll
            for (int mi = 0; mi < 4; ++mi) {
#pragma unroll
                for (int ni = 0; ni < 8; ++ni) {
                    int r = m0 + wm + mi * 16 + g;
                    int c = n0 + wn + ni * 8 + 2 * tk;
                    int h = (c >> 5) & 7;
                    int d = c & 31;
                    float b0 = v_bias[c - 512], b1 = v_bias[c - 511];
                    int bw0 = r >> 6, n_0 = r & 63;
                    int bw1 = (r + 8) >> 6, n_1 = (r + 8) & 63;
                    float2 v0 = make_float2(acc[mi][ni][0] + b0, acc[mi][ni][1] + b1);
                    float2 v1 = make_float2(acc[mi][ni][2] + b0, acc[mi][ni][3] + b1);
                    *(float2*)(g_V + (size_t)((bw0 * 8 + h) * 64 + n_0) * 32 + d) = v0;
                    *(float2*)(g_V + (size_t)((bw1 * 8 + h) * 64 + n_1) * 32 + d) = v1;
                }
            }
        } else {
            // Q or K: add bias (K bias = 0), L2-normalize per (row, head),
            // split to packed bf16 hi/lo, store to g_Qs2 / g_Ks2.
            uint32_t* dst = (which == 0) ? g_Qs2 : g_Ks2;
            int hbase = ((n0 + wn) >> 5) & 7;
#pragma unroll
            for (int mi = 0; mi < 4; ++mi) {
                int r = m0 + wm + mi * 16 + g;   // rows r, r+8
#pragma unroll
                for (int hh = 0; hh < 2; ++hh) {
                    int h = hbase + hh;
                    float v[4][4];
                    float ss0 = 0.f, ss1 = 0.f;
#pragma unroll
                    for (int nj = 0; nj < 4; ++nj) {
                        int ni = hh * 4 + nj;
                        float b0 = 0.f, b1 = 0.f;
                        if (which == 0) {
                            int c = n0 + wn + ni * 8 + 2 * tk;
                            b0 = q_bias[c];
                            b1 = q_bias[c + 1];
                        }
                        v[nj][0] = acc[mi][ni][0] + b0;
                        v[nj][1] = acc[mi][ni][1] + b1;
                        v[nj][2] = acc[mi][ni][2] + b0;
                        v[nj][3] = acc[mi][ni][3] + b1;
                        ss0 = fmaf(v[nj][0], v[nj][0], fmaf(v[nj][1], v[nj][1], ss0));
                        ss1 = fmaf(v[nj][2], v[nj][2], fmaf(v[nj][3], v[nj][3], ss1));
                    }
                    ss0 += __shfl_xor_sync(0xffffffffu, ss0, 1);
                    ss0 += __shfl_xor_sync(0xffffffffu, ss0, 2);
                    ss1 += __shfl_xor_sync(0xffffffffu, ss1, 1);
                    ss1 += __shfl_xor_sync(0xffffffffu, ss1, 2);
                    float inv0 = 1.f / fmaxf(sqrtf(ss0), 1e-12f);
                    float inv1 = 1.f / fmaxf(sqrtf(ss1), 1e-12f);
                    int bw0 = r >> 6, n_0 = r & 63;
                    int bw1 = (r + 8) >> 6, n_1 = (r + 8) & 63;
                    uint32_t* d0 = dst + (size_t)((bw0 * 8 + h) * 64 + n_0) * 32;
                    uint32_t* d1 = dst + (size_t)((bw1 * 8 + h) * 64 + n_1) * 32;
#pragma unroll
                    for (int nj = 0; nj < 4; ++nj) {
                        int kp = nj * 4 + tk;
                        uint32_t hw, lw;
                        split2_bf(v[nj][0] * inv0, v[nj][1] * inv0, hw, lw);
                        d0[kp] = hw;
                        d0[16 + kp] = lw;
                        split2_bf(v[nj][2] * inv1, v[nj][3] * inv1, hw, lw);
                        d1[kp] = hw;
                        d1[16 + kp] = lw;
                    }
                }
            }
        }
    } else {
#pragma unroll
        for (int mi = 0; mi < 4; ++mi) {
#pragma unroll
            for (int ni = 0; ni < 8; ++ni) {
                int r = m0 + wm + mi * 16 + g;
                int c = n0 + wn + ni * 8 + 2 * tk;
                float b0 = pb[c], b1 = pb[c + 1];
                float2 v0 = make_float2(acc[mi][ni][0] + b0, acc[mi][ni][1] + b1);
                float2 v1 = make_float2(acc[mi][ni][2] + b0, acc[mi][ni][3] + b1);
                *(float2*)(out + (size_t)r * 256 + c) = v0;
                *(float2*)(out + (size_t)(r + 8) * 256 + c) = v1;
            }
        }
    }
}

// ---------------------------------------------------------------------------
// bf16 mma attention. Q/K staged via cp.async from pre-normalized packed
// global (g_Qs2/g_Ks2); V transposed+split from fp32 g_V as before.
// CTA = 2 heads of one window (128 thr). Grid = BWIN*4.
// Per head smem (words): Qm 64x36 (hi at [0..15], lo [16..31], 4 pad),
// Km 64x36, VTh 32x36, VTl 32x36 -> 6912 words = 27648 B.
// ---------------------------------------------------------------------------
#define ATT_HEAD_WORDS 6912
#define ATT_SMEM_BYTES (2 * ATT_HEAD_WORDS * 4)

__global__ __launch_bounds__(128) void attn_bf16(const float* __restrict__ logit_scale)
{
    extern __shared__ uint32_t smw[];
    int tid = threadIdx.x;
    int lane = tid & 31, warp = tid >> 5;
    int b = blockIdx.x >> 2;
    int h = ((blockIdx.x & 3) << 1) + (warp >> 1);
    int hp = warp >> 1;
    int wp = warp & 1;
    int wrow = wp * 32;
    int g = lane >> 2, tk = lane & 3;

    uint32_t* Qm = smw + hp * ATT_HEAD_WORDS;
    uint32_t* Km = Qm + 2304;
    uint32_t* VTh = Km + 2304;
    uint32_t* VTl = VTh + 1152;

    // ---- stage Q,K via cp.async (pre-normalized, pre-split) ----
    {
        int ptid = tid & 63;
        const uint32_t* Qps = g_Qs2 + (size_t)(b * 8 + h) * 2048;
        const uint32_t* Kps = g_Ks2 + (size_t)(b * 8 + h) * 2048;
        uint32_t qa = smem_u32(Qm), ka = smem_u32(Km);
#pragma unroll
        for (int i = 0; i < 8; ++i) {
            int idx = ptid + 64 * i;        // 0..511
            int row = idx >> 3, c16 = idx & 7;
            uint32_t do_ = (uint32_t)(row * 144 + c16 * 16);
            CP16(qa + do_, Qps + row * 32 + c16 * 4);
            CP16(ka + do_, Kps + row * 32 + c16 * 4);
        }
        CP_COMMIT();

        // ---- V: transpose + split from fp32 ----
        const float* Vg = g_V + (size_t)(b * 8 + h) * 2048;
#pragma unroll
        for (int i = 0; i < 16; ++i) {
            int jp = wp * 16 + i;
            float v0 = Vg[(2 * jp) * 32 + lane];
            float v1 = Vg[(2 * jp + 1) * 32 + lane];
            uint32_t hw, lw;
            split2_bf(v0, v1, hw, lw);
            VTh[lane * 36 + jp] = hw;
            VTl[lane * 36 + jp] = lw;
        }
        CP_WAIT0();
    }
    __syncthreads();

    float sc = __expf(fminf(logit_scale[h], 4.6051701859880913f));

    // ---- QK^T ----
    float acc[2][8][4];
#pragma unroll
    for (int mi = 0; mi < 2; ++mi)
#pragma unroll
        for (int ni = 0; ni < 8; ++ni)
#pragma unroll
            for (int q = 0; q < 4; ++q) acc[mi][ni][q] = 0.f;

#pragma unroll
    for (int s = 0; s < 2; ++s) {
        int kp0 = 8 * s + tk, kp1 = kp0 + 4;
        uint32_t Ah[2][4], Al[2][4];
#pragma unroll
        for (int mi = 0; mi < 2; ++mi) {
            int r0 = wrow + mi * 16 + g;
            int r1 = r0 + 8;
            Ah[mi][0] = Qm[r0 * 36 + kp0];
            Ah[mi][1] = Qm[r1 * 36 + kp0];
            Ah[mi][2] = Qm[r0 * 36 + kp1];
            Ah[mi][3] = Qm[r1 * 36 + kp1];
            Al[mi][0] = Qm[r0 * 36 + 16 + kp0];
            Al[mi][1] = Qm[r1 * 36 + 16 + kp0];
            Al[mi][2] = Qm[r0 * 36 + 16 + kp1];
            Al[mi][3] = Qm[r1 * 36 + 16 + kp1];
        }
#pragma unroll
        for (int ni = 0; ni < 8; ++ni) {
            int n = ni * 8 + g;
            uint32_t bh0 = Km[n * 36 + kp0];
            uint32_t bh1 = Km[n * 36 + kp1];
            uint32_t bl0 = Km[n * 36 + 16 + kp0];
            uint32_t bl1 = Km[n * 36 + 16 + kp1];
#pragma unroll
            for (int mi = 0; mi < 2; ++mi) {
                mma16816(acc[mi][ni], Ah[mi][0], Ah[mi][1], Ah[mi][2], Ah[mi][3], bh0, bh1);
                mma16816(acc[mi][ni], Al[mi][0], Al[mi][1], Al[mi][2], Al[mi][3], bh0, bh1);
                mma16816(acc[mi][ni], Ah[mi][0], Ah[mi][1], Ah[mi][2], Ah[mi][3], bl0, bl1);
            }
        }
    }

    // ---- logits + softmax ----
    const float* bm = g_bm + (size_t)(((b & (NW - 1)) * 8 + h)) * 4096;
#pragma unroll
    for (int mi = 0; mi < 2; ++mi) {
        int rA = wrow + mi * 16 + g;
        int rB = rA + 8;
        float mxA = -1e30f, mxB = -1e30f;
#pragma unroll
        for (int ni = 0; ni < 8; ++ni) {
            int c = ni * 8 + 2 * tk;
            float2 bA = *(const float2*)(bm + rA * 64 + c);
            float2 bB = *(const float2*)(bm + rB * 64 + c);
            acc[mi][ni][0] = fmaf(sc, acc[mi][ni][0], bA.x);
            acc[mi][ni][1] = fmaf(sc, acc[mi][ni][1], bA.y);
            acc[mi][ni][2] = fmaf(sc, acc[mi][ni][2], bB.x);
            acc[mi][ni][3] = fmaf(sc, acc[mi][ni][3], bB.y);
            mxA = fmaxf(mxA, fmaxf(acc[mi][ni][0], acc[mi][ni][1]));
            mxB = fmaxf(mxB, fmaxf(acc[mi][ni][2], acc[mi][ni][3]));
        }
        mxA = fmaxf(mxA, __shfl_xor_sync(0xffffffffu, mxA, 1));
        mxA = fmaxf(mxA, __shfl_xor_sync(0xffffffffu, mxA, 2));
        mxB = fmaxf(mxB, __shfl_xor_sync(0xffffffffu, mxB, 1));
        mxB = fmaxf(mxB, __shfl_xor_sync(0xffffffffu, mxB, 2));
        float sA = 0.f, sB = 0.f;
#pragma unroll
        for (int ni = 0; ni < 8; ++ni) {
            acc[mi][ni][0] = __expf(acc[mi][ni][0] - mxA);
            acc[mi][ni][1] = __expf(acc[mi][ni][1] - mxA);
            acc[mi][ni][2] = __expf(acc[mi][ni][2] - mxB);
            acc[mi][ni][3] = __expf(acc[mi][ni][3] - mxB);
            sA += acc[mi][ni][0] + acc[mi][ni][1];
            sB += acc[mi][ni][2] + acc[mi][ni][3];
        }
        sA += __shfl_xor_sync(0xffffffffu, sA, 1);
        sA += __shfl_xor_sync(0xffffffffu, sA, 2);
        sB += __shfl_xor_sync(0xffffffffu, sB, 1);
        sB += __shfl_xor_sync(0xffffffffu, sB, 2);
        float iA = 1.f / sA, iB = 1.f / sB;
#pragma unroll
        for (int ni = 0; ni < 8; ++ni) {
            acc[mi][ni][0] *= iA;
            acc[mi][ni][1] *= iA;
            acc[mi][ni][2] *= iB;
            acc[mi][ni][3] *= iB;
        }
    }

    // ---- AV: P from registers, V from VT smem ----
    float o[2][4][4];
#pragma unroll
    for (int mi = 0; mi < 2; ++mi)
#pragma unroll
        for (int ni = 0; ni < 4; ++ni)
#pragma unroll
            for (int q = 0; q < 4; ++q) o[mi][ni][q] = 0.f;

#pragma unroll
    for (int s = 0; s < 4; ++s) {
        int kp0 = 8 * s + tk, kp1 = kp0 + 4;
        uint32_t vh0[4], vh1[4], vl0[4], vl1[4];
#pragma unroll
        for (int ni = 0; ni < 4; ++ni) {
            int n = ni * 8 + g;
            vh0[ni] = VTh[n * 36 + kp0];
            vh1[ni] = VTh[n * 36 + kp1];
            vl0[ni] = VTl[n * 36 + kp0];
            vl1[ni] = VTl[n * 36 + kp1];
        }
#pragma unroll
        for (int mi = 0; mi < 2; ++mi) {
            uint32_t pah[4], pal[4];
            split2_bf(acc[mi][2 * s][0],     acc[mi][2 * s][1],     pah[0], pal[0]);
            split2_bf(acc[mi][2 * s][2],     acc[mi][2 * s][3],     pah[1], pal[1]);
            split2_bf(acc[mi][2 * s + 1][0], acc[mi][2 * s + 1][1], pah[2], pal[2]);
            split2_bf(acc[mi][2 * s + 1][2], acc[mi][2 * s + 1][3], pah[3], pal[3]);
#pragma unroll
            for (int ni = 0; ni < 4; ++ni) {
                mma16816(o[mi][ni], pah[0], pah[1], pah[2], pah[3], vh0[ni], vh1[ni]);
                mma16816(o[mi][ni], pal[0], pal[1], pal[2], pal[3], vh0[ni], vh1[ni]);
                mma16816(o[mi][ni], pah[0], pah[1], pah[2], pah[3], vl0[ni], vl1[ni]);
            }
        }
    }

    // write O in packed layout for proj: chunk h, hi word h*32 + kp, lo +16.
    uint32_t* OgW = g_Os + (size_t)(b * 64) * 256;
#pragma unroll
    for (int mi = 0; mi < 2; ++mi) {
        int r0 = wrow + mi * 16 + g;
        int r1 = r0 + 8;
#pragma unroll
        for (int ni = 0; ni < 4; ++ni) {
            uint32_t wbase = (uint32_t)(h * 32 + ni * 4 + tk);
            uint32_t hw, lw;
            split2_bf(o[mi][ni][0], o[mi][ni][1], hw, lw);
            OgW[(size_t)r0 * 256 + wbase] = hw;
            OgW[(size_t)r0 * 256 + wbase + 16] = lw;
            split2_bf(o[mi][ni][2], o[mi][ni][3], hw, lw);
            OgW[(size_t)r1 * 256 + wbase] = hw;
            OgW[(size_t)r1 * 256 + wbase + 16] = lw;
        }
    }
}

// ---------------------------------------------------------------------------
extern "C" void kernel_launch(void* const* d_in, const int* in_sizes, int n_in,
                              void* d_out, int out_size)
{
    const float* x           = (const float*)d_in[0];
    const float* mask        = (const float*)d_in[1];
    const float* qkv_w       = (const float*)d_in[2];
    const float* q_bias      = (const float*)d_in[3];
    const float* v_bias      = (const float*)d_in[4];
    const float* logit_scale = (const float*)d_in[5];
    const float* cpb_w1      = (const float*)d_in[6];
    const float* cpb_b1      = (const float*)d_in[7];
    const float* cpb_w2      = (const float*)d_in[8];
    const float* proj_w      = (const float*)d_in[9];
    const float* proj_b      = (const float*)d_in[10];
    const float* coords      = (const float*)d_in[11];
    const int*   rel_idx     = (const int*)d_in[12];
    float* out = (float*)d_out;

    static int configured = 0;
    if (!configured) {
        cudaFuncSetAttribute(mma_gemm, cudaFuncAttributeMaxDynamicSharedMemorySize,
                             GSMEM_TOTAL);
        cudaFuncSetAttribute(attn_bf16, cudaFuncAttributeMaxDynamicSharedMemorySize,
                             ATT_SMEM_BYTES);
        configured = 1;
    }

    // Launch order puts qkv mma_gemm at position 6 (ncu -s 5 -c 1 profiles it).
    cpb_table_kernel<<<TBL, 128>>>(cpb_w1, cpb_b1, cpb_w2, coords);          // 1
    bias_gather_kernel<<<(HEADS * SEQ * SEQ + 255) / 256, 256>>>(rel_idx);   // 2
    bm_fuse_kernel<<<(NW * HEADS * SEQ * SEQ + 255) / 256, 256>>>(mask);     // 3

    {
        void* dst;
        cudaGetSymbolAddress(&dst, g_Xs);
        split_pack<<<(BWIN * SEQ * DIM / 8 + 255) / 256, 256>>>(x, (uint32_t*)dst,
                                                                BWIN * SEQ * DIM / 8); // 4
        cudaGetSymbolAddress(&dst, g_Ws);
        split_pack<<<(3 * DIM * DIM / 8 + 255) / 256, 256>>>(qkv_w, (uint32_t*)dst,
                                                             3 * DIM * DIM / 8);       // 5
    }

    mma_gemm<<<dim3(6, 1024), 128, GSMEM_TOTAL>>>(q_bias, v_bias,
                                                  nullptr, nullptr, 0);      // 6 (profiled)
    attn_bf16<<<BWIN * 4, 128, ATT_SMEM_BYTES>>>(logit_scale);               // 7

    {
        void* dst;
        cudaGetSymbolAddress(&dst, g_Wp);
        split_pack<<<(DIM * DIM / 8 + 255) / 256, 256>>>(proj_w, (uint32_t*)dst,
                                                         DIM * DIM / 8);     // 8
    }
    mma_gemm<<<dim3(2, 1024), 128, GSMEM_TOTAL>>>(nullptr, nullptr,
                                                  proj_b, out, 1);           // 9
}

// round 17
// speedup vs baseline: 1.5247x; 1.0089x over previous
#include <cuda_runtime.h>
#include <cuda_bf16.h>
#include <cstdint>
#include <math.h>

// Problem constants
#define BWIN   2048
#define SEQ    64
#define DIM    256
#define HEADS  8
#define HD     32
#define NW     64
#define KDIM   256
#define TBL    225
#define CPBH   512

// Scratch (device globals)
__device__ float g_V[BWIN * HEADS * SEQ * HD];
__device__ float g_table[TBL * HEADS];
__device__ float g_bias[HEADS * SEQ * SEQ];
__device__ float g_bm[NW * HEADS * SEQ * SEQ];     // fused bias+mask

// Pre-split packed operands. GEMM inputs: per 256-K row, 8 chunks of 32 words,
// chunk = [hi k-pairs 0..15][lo 16..31].
__device__ uint32_t g_Xs[(size_t)BWIN * SEQ * DIM];   // 128 MB
__device__ uint32_t g_Os[(size_t)BWIN * SEQ * DIM];   // 128 MB
__device__ uint32_t g_Ws[3 * DIM * DIM];
__device__ uint32_t g_Wp[DIM * DIM];
// Pre-normalized, pre-split Q/K: per (b,h): 64 rows x 32 words [hi16|lo16]
__device__ uint32_t g_Qs2[(size_t)BWIN * HEADS * SEQ * 32];   // 134 MB
__device__ uint32_t g_Ks2[(size_t)BWIN * HEADS * SEQ * 32];   // 134 MB

// SW128 swizzle on byte offsets (128B rows)
#define SWZ(b) ((b) ^ (((b) >> 3) & 0x70))

__device__ __forceinline__ uint32_t smem_u32(const void* p) {
    uint32_t a;
    asm("{ .reg .u64 t; cvta.to.shared.u64 t, %1; cvt.u32.u64 %0, t; }"
        : "=r"(a) : "l"(p));
    return a;
}

#define CP16(dst_u32, src_ptr) \
    asm volatile("cp.async.cg.shared.global [%0], [%1], 16;" \
        :: "r"(dst_u32), "l"(src_ptr) : "memory")
#define CP_COMMIT() asm volatile("cp.async.commit_group;" ::: "memory")
#define CP_WAIT0()  asm volatile("cp.async.wait_group 0;" ::: "memory")
#define CP_WAIT1()  asm volatile("cp.async.wait_group 1;" ::: "memory")

// bf16 2-level split of two floats, packed (f0 in low half)
__device__ __forceinline__ void split2_bf(float f0, float f1,
                                          uint32_t& hi, uint32_t& lo)
{
    __nv_bfloat16 h0 = __float2bfloat16_rn(f0);
    __nv_bfloat16 h1 = __float2bfloat16_rn(f1);
    float r0 = f0 - __bfloat162float(h0);
    float r1 = f1 - __bfloat162float(h1);
    __nv_bfloat16 l0 = __float2bfloat16_rn(r0);
    __nv_bfloat16 l1 = __float2bfloat16_rn(r1);
    hi = (uint32_t)__bfloat16_as_ushort(h0) | ((uint32_t)__bfloat16_as_ushort(h1) << 16);
    lo = (uint32_t)__bfloat16_as_ushort(l0) | ((uint32_t)__bfloat16_as_ushort(l1) << 16);
}

__device__ __forceinline__ void mma16816(float* c,
    uint32_t a0, uint32_t a1, uint32_t a2, uint32_t a3,
    uint32_t b0, uint32_t b1)
{
    asm volatile(
        "mma.sync.aligned.m16n8k16.row.col.f32.bf16.bf16.f32 "
        "{%0,%1,%2,%3},{%4,%5,%6,%7},{%8,%9},{%0,%1,%2,%3};"
        : "+f"(c[0]), "+f"(c[1]), "+f"(c[2]), "+f"(c[3])
        : "r"(a0), "r"(a1), "r"(a2), "r"(a3), "r"(b0), "r"(b1));
}

__device__ __forceinline__ void ldsm4(uint32_t& r0, uint32_t& r1,
                                      uint32_t& r2, uint32_t& r3, uint32_t a)
{
    asm volatile("ldmatrix.sync.aligned.m8n8.x4.shared.b16 {%0,%1,%2,%3}, [%4];"
        : "=r"(r0), "=r"(r1), "=r"(r2), "=r"(r3) : "r"(a));
}

// ---------------------------------------------------------------------------
// split_pack: fp32 -> packed layout: per 32-float chunk, hi words 0-15, lo 16-31.
// ---------------------------------------------------------------------------
__global__ __launch_bounds__(256) void split_pack(
    const float* __restrict__ src, uint32_t* __restrict__ dst, int n_granules)
{
    int gidx = blockIdx.x * 256 + threadIdx.x;
    if (gidx >= n_granules) return;
    int chunk = gidx >> 2, gp = gidx & 3;
    const float4* s = (const float4*)(src + (size_t)gidx * 8);
    float4 v0 = s[0], v1 = s[1];
    uint32_t h0, l0, h1, l1, h2, l2, h3, l3;
    split2_bf(v0.x, v0.y, h0, l0);
    split2_bf(v0.z, v0.w, h1, l1);
    split2_bf(v1.x, v1.y, h2, l2);
    split2_bf(v1.z, v1.w, h3, l3);
    uint32_t* drow = dst + (size_t)chunk * 32;
    *(uint4*)(drow + gp * 4) = make_uint4(h0, h1, h2, h3);
    *(uint4*)(drow + 16 + gp * 4) = make_uint4(l0, l1, l2, l3);
}

// ---------------------------------------------------------------------------
// Kernel 1: CPB MLP
// ---------------------------------------------------------------------------
__global__ __launch_bounds__(128) void cpb_table_kernel(
    const float* __restrict__ w1, const float* __restrict__ b1,
    const float* __restrict__ w2, const float* __restrict__ coords)
{
    int p = blockIdx.x;
    float c0 = coords[2 * p + 0];
    float c1 = coords[2 * p + 1];
    float acc[HEADS];
#pragma unroll
    for (int h = 0; h < HEADS; ++h) acc[h] = 0.f;

    for (int j = threadIdx.x; j < CPBH; j += 128) {
        float hid = fmaf(w1[2 * j], c0, fmaf(w1[2 * j + 1], c1, b1[j]));
        hid = fmaxf(hid, 0.f);
#pragma unroll
        for (int h = 0; h < HEADS; ++h)
            acc[h] = fmaf(hid, w2[h * CPBH + j], acc[h]);
    }
    int lane = threadIdx.x & 31, warp = threadIdx.x >> 5;
#pragma unroll
    for (int h = 0; h < HEADS; ++h)
#pragma unroll
        for (int off = 16; off; off >>= 1)
            acc[h] += __shfl_xor_sync(0xffffffffu, acc[h], off);

    __shared__ float red[4][HEADS];
    if (lane == 0)
#pragma unroll
        for (int h = 0; h < HEADS; ++h) red[warp][h] = acc[h];
    __syncthreads();
    if (threadIdx.x < HEADS) {
        float s = red[0][threadIdx.x] + red[1][threadIdx.x] +
                  red[2][threadIdx.x] + red[3][threadIdx.x];
        g_table[p * HEADS + threadIdx.x] = s;
    }
}

// ---------------------------------------------------------------------------
// Kernel 2: bias gather + 16*sigmoid
// ---------------------------------------------------------------------------
__global__ __launch_bounds__(256) void bias_gather_kernel(const int* __restrict__ rel_idx)
{
    int i = blockIdx.x * 256 + threadIdx.x;
    if (i >= HEADS * SEQ * SEQ) return;
    int h = i >> 12;
    int ij = i & 4095;
    float t = g_table[rel_idx[ij] * HEADS + h];
    g_bias[i] = 16.f / (1.f + expf(-t));
}

// ---------------------------------------------------------------------------
// Kernel 2b: fuse bias[h] + mask[w] -> g_bm[w][h][ij]
// ---------------------------------------------------------------------------
__global__ __launch_bounds__(256) void bm_fuse_kernel(const float* __restrict__ mask)
{
    int i = blockIdx.x * 256 + threadIdx.x;
    if (i >= NW * HEADS * SEQ * SEQ) return;
    int wh = i >> 12;
    int ij = i & 4095;
    int w = wh >> 3, h = wh & 7;
    g_bm[i] = g_bias[h * 4096 + ij] + mask[w * 4096 + ij];
}

// ---------------------------------------------------------------------------
// 3-term bf16 mma.sync GEMM, ldmatrix fragment loads, TRIPLE-buffered
// cp.async pipeline (one __syncthreads per chunk).
// 128 threads (4 warps, 64x64 tiles). CTA 128x128, BK=32, K=256 (8 chunks).
// smem: 3 x (A 16KB + B 16KB) = 96KB.
// mode 0 epilogue: Q/K normalized+split to g_Qs2/g_Ks2; V fp32 to g_V.
// ---------------------------------------------------------------------------
#define GSMEM_TOTAL (3 * 32768)

__global__ __launch_bounds__(128, 2) void mma_gemm(
    const float* __restrict__ q_bias, const float* __restrict__ v_bias,
    const float* __restrict__ pb, float* __restrict__ out, int mode)
{
    extern __shared__ char sm[];
    uint32_t sb = smem_u32(sm);
    const uint32_t* As = (mode == 0) ? g_Xs : g_Os;
    const uint32_t* Bsrc = (mode == 0) ? g_Ws : g_Wp;
    int tid = threadIdx.x;
    int lane = tid & 31, warp = tid >> 5;
    int m0 = blockIdx.y * 128;
    int n0 = blockIdx.x * 128;
    int wm = (warp >> 1) * 64;
    int wn = (warp & 1) * 64;

    float acc[4][8][4];
#pragma unroll
    for (int mi = 0; mi < 4; ++mi)
#pragma unroll
        for (int ni = 0; ni < 8; ++ni)
#pragma unroll
            for (int q = 0; q < 4; ++q) acc[mi][ni][q] = 0.f;

    int g = lane >> 2;       // 0..7
    int tk = lane & 3;       // 0..3

    int a_row_l = lane & 15;
    uint32_t a_cb16 = ((lane >> 4) & 1) * 16u;
    int b_nrow_l = ((lane >> 4) & 1) * 8 + (lane & 7);
    uint32_t b_cb16 = ((lane >> 3) & 1) * 16u;

#define ISSUE_STAGE(c) do { \
    uint32_t dbuf = sb + (uint32_t)(((c) % 3) * 32768); \
    const uint32_t* arow = As + (size_t)(m0 + tid) * 256 + (c) * 32; \
    const uint32_t* brow = Bsrc + (size_t)(n0 + tid) * 256 + (c) * 32; \
    _Pragma("unroll") \
    for (int gp = 0; gp < 4; ++gp) { \
        uint32_t o_ = (uint32_t)(tid * 128 + gp * 32); \
        CP16(dbuf + SWZ(o_), arow + gp * 8); \
        CP16(dbuf + SWZ(o_ + 16u), arow + gp * 8 + 4); \
        CP16(dbuf + 16384u + SWZ(o_), brow + gp * 8); \
        CP16(dbuf + 16384u + SWZ(o_ + 16u), brow + gp * 8 + 4); \
    } \
    CP_COMMIT(); \
} while (0)

    ISSUE_STAGE(0);
    ISSUE_STAGE(1);

    for (int c = 0; c < 8; ++c) {
        if (c < 7) { CP_WAIT1(); }
        else       { CP_WAIT0(); }
        __syncthreads();
        if (c < 6) ISSUE_STAGE(c + 2);   // buffer (c+2)%3: chunk c-1 compute done

        uint32_t sAb = sb + (uint32_t)((c % 3) * 32768);
        uint32_t sBb = sAb + 16384u;
#pragma unroll
        for (int s = 0; s < 2; ++s) {
            uint32_t Ah[4][4], Al[4][4];
#pragma unroll
            for (int mi = 0; mi < 4; ++mi) {
                int row = wm + mi * 16 + a_row_l;
                uint32_t xr = ((uint32_t)(row & 7)) << 4;
                uint32_t cb = ((uint32_t)(32 * s) + a_cb16) ^ xr;
                uint32_t addr = sAb + (uint32_t)(row * 128) + cb;
                ldsm4(Ah[mi][0], Ah[mi][1], Ah[mi][2], Ah[mi][3], addr);
                uint32_t addrl = sAb + (uint32_t)(row * 128) + (cb ^ 64u);
                ldsm4(Al[mi][0], Al[mi][1], Al[mi][2], Al[mi][3], addrl);
            }
#pragma unroll
            for (int p = 0; p < 4; ++p) {
                int nrow = wn + p * 16 + b_nrow_l;
                uint32_t xr = ((uint32_t)(nrow & 7)) << 4;
                uint32_t cb = ((uint32_t)(32 * s) + b_cb16) ^ xr;
                uint32_t baddr = sBb + (uint32_t)(nrow * 128) + cb;
                uint32_t bh0, bh1, bh2, bh3, bl0, bl1, bl2, bl3;
                ldsm4(bh0, bh1, bh2, bh3, baddr);
                uint32_t baddl = sBb + (uint32_t)(nrow * 128) + (cb ^ 64u);
                ldsm4(bl0, bl1, bl2, bl3, baddl);
#pragma unroll
                for (int mi = 0; mi < 4; ++mi) {
                    mma16816(acc[mi][2 * p], Ah[mi][0], Ah[mi][1], Ah[mi][2], Ah[mi][3], bh0, bh1);
                    mma16816(acc[mi][2 * p], Al[mi][0], Al[mi][1], Al[mi][2], Al[mi][3], bh0, bh1);
                    mma16816(acc[mi][2 * p], Ah[mi][0], Ah[mi][1], Ah[mi][2], Ah[mi][3], bl0, bl1);
                }
#pragma unroll
                for (int mi = 0; mi < 4; ++mi) {
                    mma16816(acc[mi][2 * p + 1], Ah[mi][0], Ah[mi][1], Ah[mi][2], Ah[mi][3], bh2, bh3);
                    mma16816(acc[mi][2 * p + 1], Al[mi][0], Al[mi][1], Al[mi][2], Al[mi][3], bh2, bh3);
                    mma16816(acc[mi][2 * p + 1], Ah[mi][0], Ah[mi][1], Ah[mi][2], Ah[mi][3], bl2, bl3);
                }
            }
        }
    }

    // Epilogue
    if (mode == 0) {
        int which = (n0 + wn) >> 8;   // 0=Q, 1=K, 2=V (uniform over warp)
        if (which == 2) {
#pragma unroll
            for (int mi = 0; mi < 4; ++mi) {
#pragma unroll
                for (int ni = 0; ni < 8; ++ni) {
                    int r = m0 + wm + mi * 16 + g;
                    int c = n0 + wn + ni * 8 + 2 * tk;
                    int h = (c >> 5) & 7;
                    int d = c & 31;
                    float b0 = v_bias[c - 512], b1 = v_bias[c - 511];
                    int bw0 = r >> 6, n_0 = r & 63;
                    int bw1 = (r + 8) >> 6, n_1 = (r + 8) & 63;
                    float2 v0 = make_float2(acc[mi][ni][0] + b0, acc[mi][ni][1] + b1);
                    float2 v1 = make_float2(acc[mi][ni][2] + b0, acc[mi][ni][3] + b1);
                    *(float2*)(g_V + (size_t)((bw0 * 8 + h) * 64 + n_0) * 32 + d) = v0;
                    *(float2*)(g_V + (size_t)((bw1 * 8 + h) * 64 + n_1) * 32 + d) = v1;
                }
            }
        } else {
            uint32_t* dst = (which == 0) ? g_Qs2 : g_Ks2;
            int hbase = ((n0 + wn) >> 5) & 7;
#pragma unroll
            for (int mi = 0; mi < 4; ++mi) {
                int r = m0 + wm + mi * 16 + g;   // rows r, r+8
#pragma unroll
                for (int hh = 0; hh < 2; ++hh) {
                    int h = hbase + hh;
                    float v[4][4];
                    float ss0 = 0.f, ss1 = 0.f;
#pragma unroll
                    for (int nj = 0; nj < 4; ++nj) {
                        int ni = hh * 4 + nj;
                        float b0 = 0.f, b1 = 0.f;
                        if (which == 0) {
                            int c = n0 + wn + ni * 8 + 2 * tk;
                            b0 = q_bias[c];
                            b1 = q_bias[c + 1];
                        }
                        v[nj][0] = acc[mi][ni][0] + b0;
                        v[nj][1] = acc[mi][ni][1] + b1;
                        v[nj][2] = acc[mi][ni][2] + b0;
                        v[nj][3] = acc[mi][ni][3] + b1;
                        ss0 = fmaf(v[nj][0], v[nj][0], fmaf(v[nj][1], v[nj][1], ss0));
                        ss1 = fmaf(v[nj][2], v[nj][2], fmaf(v[nj][3], v[nj][3], ss1));
                    }
                    ss0 += __shfl_xor_sync(0xffffffffu, ss0, 1);
                    ss0 += __shfl_xor_sync(0xffffffffu, ss0, 2);
                    ss1 += __shfl_xor_sync(0xffffffffu, ss1, 1);
                    ss1 += __shfl_xor_sync(0xffffffffu, ss1, 2);
                    float inv0 = 1.f / fmaxf(sqrtf(ss0), 1e-12f);
                    float inv1 = 1.f / fmaxf(sqrtf(ss1), 1e-12f);
                    int bw0 = r >> 6, n_0 = r & 63;
                    int bw1 = (r + 8) >> 6, n_1 = (r + 8) & 63;
                    uint32_t* d0 = dst + (size_t)((bw0 * 8 + h) * 64 + n_0) * 32;
                    uint32_t* d1 = dst + (size_t)((bw1 * 8 + h) * 64 + n_1) * 32;
#pragma unroll
                    for (int nj = 0; nj < 4; ++nj) {
                        int kp = nj * 4 + tk;
                        uint32_t hw, lw;
                        split2_bf(v[nj][0] * inv0, v[nj][1] * inv0, hw, lw);
                        d0[kp] = hw;
                        d0[16 + kp] = lw;
                        split2_bf(v[nj][2] * inv1, v[nj][3] * inv1, hw, lw);
                        d1[kp] = hw;
                        d1[16 + kp] = lw;
                    }
                }
            }
        }
    } else {
#pragma unroll
        for (int mi = 0; mi < 4; ++mi) {
#pragma unroll
            for (int ni = 0; ni < 8; ++ni) {
                int r = m0 + wm + mi * 16 + g;
                int c = n0 + wn + ni * 8 + 2 * tk;
                float b0 = pb[c], b1 = pb[c + 1];
                float2 v0 = make_float2(acc[mi][ni][0] + b0, acc[mi][ni][1] + b1);
                float2 v1 = make_float2(acc[mi][ni][2] + b0, acc[mi][ni][3] + b1);
                *(float2*)(out + (size_t)r * 256 + c) = v0;
                *(float2*)(out + (size_t)(r + 8) * 256 + c) = v1;
            }
        }
    }
}

// ---------------------------------------------------------------------------
// bf16 mma attention (R16-proven). Q/K via cp.async from pre-normalized
// packed global; V transposed+split from fp32 g_V.
// ---------------------------------------------------------------------------
#define ATT_HEAD_WORDS 6912
#define ATT_SMEM_BYTES (2 * ATT_HEAD_WORDS * 4)

__global__ __launch_bounds__(128) void attn_bf16(const float* __restrict__ logit_scale)
{
    extern __shared__ uint32_t smw[];
    int tid = threadIdx.x;
    int lane = tid & 31, warp = tid >> 5;
    int b = blockIdx.x >> 2;
    int h = ((blockIdx.x & 3) << 1) + (warp >> 1);
    int hp = warp >> 1;
    int wp = warp & 1;
    int wrow = wp * 32;
    int g = lane >> 2, tk = lane & 3;

    uint32_t* Qm = smw + hp * ATT_HEAD_WORDS;
    uint32_t* Km = Qm + 2304;
    uint32_t* VTh = Km + 2304;
    uint32_t* VTl = VTh + 1152;

    {
        int ptid = tid & 63;
        const uint32_t* Qps = g_Qs2 + (size_t)(b * 8 + h) * 2048;
        const uint32_t* Kps = g_Ks2 + (size_t)(b * 8 + h) * 2048;
        uint32_t qa = smem_u32(Qm), ka = smem_u32(Km);
#pragma unroll
        for (int i = 0; i < 8; ++i) {
            int idx = ptid + 64 * i;
            int row = idx >> 3, c16 = idx & 7;
            uint32_t do_ = (uint32_t)(row * 144 + c16 * 16);
            CP16(qa + do_, Qps + row * 32 + c16 * 4);
            CP16(ka + do_, Kps + row * 32 + c16 * 4);
        }
        CP_COMMIT();

        const float* Vg = g_V + (size_t)(b * 8 + h) * 2048;
#pragma unroll
        for (int i = 0; i < 16; ++i) {
            int jp = wp * 16 + i;
            float v0 = Vg[(2 * jp) * 32 + lane];
            float v1 = Vg[(2 * jp + 1) * 32 + lane];
            uint32_t hw, lw;
            split2_bf(v0, v1, hw, lw);
            VTh[lane * 36 + jp] = hw;
            VTl[lane * 36 + jp] = lw;
        }
        CP_WAIT0();
    }
    __syncthreads();

    float sc = __expf(fminf(logit_scale[h], 4.6051701859880913f));

    float acc[2][8][4];
#pragma unroll
    for (int mi = 0; mi < 2; ++mi)
#pragma unroll
        for (int ni = 0; ni < 8; ++ni)
#pragma unroll
            for (int q = 0; q < 4; ++q) acc[mi][ni][q] = 0.f;

#pragma unroll
    for (int s = 0; s < 2; ++s) {
        int kp0 = 8 * s + tk, kp1 = kp0 + 4;
        uint32_t Ah[2][4], Al[2][4];
#pragma unroll
        for (int mi = 0; mi < 2; ++mi) {
            int r0 = wrow + mi * 16 + g;
            int r1 = r0 + 8;
            Ah[mi][0] = Qm[r0 * 36 + kp0];
            Ah[mi][1] = Qm[r1 * 36 + kp0];
            Ah[mi][2] = Qm[r0 * 36 + kp1];
            Ah[mi][3] = Qm[r1 * 36 + kp1];
            Al[mi][0] = Qm[r0 * 36 + 16 + kp0];
            Al[mi][1] = Qm[r1 * 36 + 16 + kp0];
            Al[mi][2] = Qm[r0 * 36 + 16 + kp1];
            Al[mi][3] = Qm[r1 * 36 + 16 + kp1];
        }
#pragma unroll
        for (int ni = 0; ni < 8; ++ni) {
            int n = ni * 8 + g;
            uint32_t bh0 = Km[n * 36 + kp0];
            uint32_t bh1 = Km[n * 36 + kp1];
            uint32_t bl0 = Km[n * 36 + 16 + kp0];
            uint32_t bl1 = Km[n * 36 + 16 + kp1];
#pragma unroll
            for (int mi = 0; mi < 2; ++mi) {
                mma16816(acc[mi][ni], Ah[mi][0], Ah[mi][1], Ah[mi][2], Ah[mi][3], bh0, bh1);
                mma16816(acc[mi][ni], Al[mi][0], Al[mi][1], Al[mi][2], Al[mi][3], bh0, bh1);
                mma16816(acc[mi][ni], Ah[mi][0], Ah[mi][1], Ah[mi][2], Ah[mi][3], bl0, bl1);
            }
        }
    }

    const float* bm = g_bm + (size_t)(((b & (NW - 1)) * 8 + h)) * 4096;
#pragma unroll
    for (int mi = 0; mi < 2; ++mi) {
        int rA = wrow + mi * 16 + g;
        int rB = rA + 8;
        float mxA = -1e30f, mxB = -1e30f;
#pragma unroll
        for (int ni = 0; ni < 8; ++ni) {
            int c = ni * 8 + 2 * tk;
            float2 bA = *(const float2*)(bm + rA * 64 + c);
            float2 bB = *(const float2*)(bm + rB * 64 + c);
            acc[mi][ni][0] = fmaf(sc, acc[mi][ni][0], bA.x);
            acc[mi][ni][1] = fmaf(sc, acc[mi][ni][1], bA.y);
            acc[mi][ni][2] = fmaf(sc, acc[mi][ni][2], bB.x);
            acc[mi][ni][3] = fmaf(sc, acc[mi][ni][3], bB.y);
            mxA = fmaxf(mxA, fmaxf(acc[mi][ni][0], acc[mi][ni][1]));
            mxB = fmaxf(mxB, fmaxf(acc[mi][ni][2], acc[mi][ni][3]));
        }
        mxA = fmaxf(mxA, __shfl_xor_sync(0xffffffffu, mxA, 1));
        mxA = fmaxf(mxA, __shfl_xor_sync(0xffffffffu, mxA, 2));
        mxB = fmaxf(mxB, __shfl_xor_sync(0xffffffffu, mxB, 1));
        mxB = fmaxf(mxB, __shfl_xor_sync(0xffffffffu, mxB, 2));
        float sA = 0.f, sB = 0.f;
#pragma unroll
        for (int ni = 0; ni < 8; ++ni) {
            acc[mi][ni][0] = __expf(acc[mi][ni][0] - mxA);
            acc[mi][ni][1] = __expf(acc[mi][ni][1] - mxA);
            acc[mi][ni][2] = __expf(acc[mi][ni][2] - mxB);
            acc[mi][ni][3] = __expf(acc[mi][ni][3] - mxB);
            sA += acc[mi][ni][0] + acc[mi][ni][1];
            sB += acc[mi][ni][2] + acc[mi][ni][3];
        }
        sA += __shfl_xor_sync(0xffffffffu, sA, 1);
        sA += __shfl_xor_sync(0xffffffffu, sA, 2);
        sB += __shfl_xor_sync(0xffffffffu, sB, 1);
        sB += __shfl_xor_sync(0xffffffffu, sB, 2);
        float iA = 1.f / sA, iB = 1.f / sB;
#pragma unroll
        for (int ni = 0; ni < 8; ++ni) {
            acc[mi][ni][0] *= iA;
            acc[mi][ni][1] *= iA;
            acc[mi][ni][2] *= iB;
            acc[mi][ni][3] *= iB;
        }
    }

    float o[2][4][4];
#pragma unroll
    for (int mi = 0; mi < 2; ++mi)
#pragma unroll
        for (int ni = 0; ni < 4; ++ni)
#pragma unroll
            for (int q = 0; q < 4; ++q) o[mi][ni][q] = 0.f;

#pragma unroll
    for (int s = 0; s < 4; ++s) {
        int kp0 = 8 * s + tk, kp1 = kp0 + 4;
        uint32_t vh0[4], vh1[4], vl0[4], vl1[4];
#pragma unroll
        for (int ni = 0; ni < 4; ++ni) {
            int n = ni * 8 + g;
            vh0[ni] = VTh[n * 36 + kp0];
            vh1[ni] = VTh[n * 36 + kp1];
            vl0[ni] = VTl[n * 36 + kp0];
            vl1[ni] = VTl[n * 36 + kp1];
        }
#pragma unroll
        for (int mi = 0; mi < 2; ++mi) {
            uint32_t pah[4], pal[4];
            split2_bf(acc[mi][2 * s][0],     acc[mi][2 * s][1],     pah[0], pal[0]);
            split2_bf(acc[mi][2 * s][2],     acc[mi][2 * s][3],     pah[1], pal[1]);
            split2_bf(acc[mi][2 * s + 1][0], acc[mi][2 * s + 1][1], pah[2], pal[2]);
            split2_bf(acc[mi][2 * s + 1][2], acc[mi][2 * s + 1][3], pah[3], pal[3]);
#pragma unroll
            for (int ni = 0; ni < 4; ++ni) {
                mma16816(o[mi][ni], pah[0], pah[1], pah[2], pah[3], vh0[ni], vh1[ni]);
                mma16816(o[mi][ni], pal[0], pal[1], pal[2], pal[3], vh0[ni], vh1[ni]);
                mma16816(o[mi][ni], pah[0], pah[1], pah[2], pah[3], vl0[ni], vl1[ni]);
            }
        }
    }

    uint32_t* OgW = g_Os + (size_t)(b * 64) * 256;
#pragma unroll
    for (int mi = 0; mi < 2; ++mi) {
        int r0 = wrow + mi * 16 + g;
        int r1 = r0 + 8;
#pragma unroll
        for (int ni = 0; ni < 4; ++ni) {
            uint32_t wbase = (uint32_t)(h * 32 + ni * 4 + tk);
            uint32_t hw, lw;
            split2_bf(o[mi][ni][0], o[mi][ni][1], hw, lw);
            OgW[(size_t)r0 * 256 + wbase] = hw;
            OgW[(size_t)r0 * 256 + wbase + 16] = lw;
            split2_bf(o[mi][ni][2], o[mi][ni][3], hw, lw);
            OgW[(size_t)r1 * 256 + wbase] = hw;
            OgW[(size_t)r1 * 256 + wbase + 16] = lw;
        }
    }
}

// ---------------------------------------------------------------------------
extern "C" void kernel_launch(void* const* d_in, const int* in_sizes, int n_in,
                              void* d_out, int out_size)
{
    const float* x           = (const float*)d_in[0];
    const float* mask        = (const float*)d_in[1];
    const float* qkv_w       = (const float*)d_in[2];
    const float* q_bias      = (const float*)d_in[3];
    const float* v_bias      = (const float*)d_in[4];
    const float* logit_scale = (const float*)d_in[5];
    const float* cpb_w1      = (const float*)d_in[6];
    const float* cpb_b1      = (const float*)d_in[7];
    const float* cpb_w2      = (const float*)d_in[8];
    const float* proj_w      = (const float*)d_in[9];
    const float* proj_b      = (const float*)d_in[10];
    const float* coords      = (const float*)d_in[11];
    const int*   rel_idx     = (const int*)d_in[12];
    float* out = (float*)d_out;

    static int configured = 0;
    if (!configured) {
        cudaFuncSetAttribute(mma_gemm, cudaFuncAttributeMaxDynamicSharedMemorySize,
                             GSMEM_TOTAL);
        cudaFuncSetAttribute(attn_bf16, cudaFuncAttributeMaxDynamicSharedMemorySize,
                             ATT_SMEM_BYTES);
        configured = 1;
    }

    // qkv mma_gemm is launch #6 (ncu -s 5 -c 1 profiles it).
    cpb_table_kernel<<<TBL, 128>>>(cpb_w1, cpb_b1, cpb_w2, coords);          // 1
    bias_gather_kernel<<<(HEADS * SEQ * SEQ + 255) / 256, 256>>>(rel_idx);   // 2
    bm_fuse_kernel<<<(NW * HEADS * SEQ * SEQ + 255) / 256, 256>>>(mask);     // 3

    {
        void* dst;
        cudaGetSymbolAddress(&dst, g_Xs);
        split_pack<<<(BWIN * SEQ * DIM / 8 + 255) / 256, 256>>>(x, (uint32_t*)dst,
                                                                BWIN * SEQ * DIM / 8); // 4
        cudaGetSymbolAddress(&dst, g_Ws);
        split_pack<<<(3 * DIM * DIM / 8 + 255) / 256, 256>>>(qkv_w, (uint32_t*)dst,
                                                             3 * DIM * DIM / 8);       // 5
    }

    mma_gemm<<<dim3(6, 1024), 128, GSMEM_TOTAL>>>(q_bias, v_bias,
                                                  nullptr, nullptr, 0);      // 6 (profiled)
    attn_bf16<<<BWIN * 4, 128, ATT_SMEM_BYTES>>>(logit_scale);               // 7

    {
        void* dst;
        cudaGetSymbolAddress(&dst, g_Wp);
        split_pack<<<(DIM * DIM / 8 + 255) / 256, 256>>>(proj_w, (uint32_t*)dst,
                                                         DIM * DIM / 8);     // 8
    }
    mma_gemm<<<dim3(2, 1024), 128, GSMEM_TOTAL>>>(nullptr, nullptr,
                                                  proj_b, out, 1);           // 9
}